// round 4
// baseline (speedup 1.0000x reference)
#include <cuda_runtime.h>
#include <math.h>
#include <stdint.h>

// ---------------- problem constants ----------------
#define BB 256
#define HWD 196      // 14*14
#define CD 512
#define TS_INV (1.0f/0.03f)
#define TC_INV (1.0f/0.07f)

// ---------------- scratch (device globals; no runtime allocation) ----------------
__device__ float d_hfc[BB*CD];
__device__ float d_fa[BB*CD];
__device__ float d_faT[CD*BB];
__device__ float d_h1[BB*CD*HWD];     // relu(conv1) 102.8 MB
__device__ float d_fv[BB*CD*HWD];     // conv2 output 102.8 MB
__device__ float d_ind[BB*CD];
__device__ float d_ivn[BB*CD];
__device__ float d_ivnT[CD*BB];
__device__ float d_invrho[BB*HWD];
__device__ float d_Sij[BB*BB*HWD];    // 51.4 MB
__device__ float d_SP[BB*BB];
__device__ float d_SN[BB*BB];
__device__ float d_E[BB*BB];
__device__ float d_l1[BB];
__device__ float d_l2[BB];
// packed bf16x2 split weights: [t][oc][icpair]
__device__ uint32_t d_wH1[9*512*192];
__device__ uint32_t d_wL1[9*512*192];
__device__ uint32_t d_wH2[9*512*256];
__device__ uint32_t d_wL2[9*512*256];

// ---------------- reduction helpers ----------------
__device__ __forceinline__ float warpReduceSum(float v) {
#pragma unroll
    for (int o = 16; o > 0; o >>= 1) v += __shfl_xor_sync(0xffffffffu, v, o);
    return v;
}
__device__ __forceinline__ float warpReduceMax(float v) {
#pragma unroll
    for (int o = 16; o > 0; o >>= 1) v = fmaxf(v, __shfl_xor_sync(0xffffffffu, v, o));
    return v;
}
__device__ __forceinline__ float blockReduceSum(float v, float* red) {
    __syncthreads();
    int lane = threadIdx.x & 31, wid = threadIdx.x >> 5;
    v = warpReduceSum(v);
    if (lane == 0) red[wid] = v;
    __syncthreads();
    int nw = (blockDim.x + 31) >> 5;
    if (wid == 0) {
        float r = (threadIdx.x < nw) ? red[threadIdx.x] : 0.f;
        r = warpReduceSum(r);
        if (lane == 0) red[0] = r;
    }
    __syncthreads();
    return red[0];
}
__device__ __forceinline__ float blockReduceMax(float v, float* red) {
    __syncthreads();
    int lane = threadIdx.x & 31, wid = threadIdx.x >> 5;
    v = warpReduceMax(v);
    if (lane == 0) red[wid] = v;
    __syncthreads();
    int nw = (blockDim.x + 31) >> 5;
    if (wid == 0) {
        float r = (threadIdx.x < nw) ? red[threadIdx.x] : -INFINITY;
        r = warpReduceMax(r);
        if (lane == 0) red[0] = r;
    }
    __syncthreads();
    return red[0];
}

__device__ __forceinline__ float sigmoidf_stable(float x) {
    if (x >= 0.f) { float e = expf(-x); return 1.f / (1.f + e); }
    float e = expf(x); return e / (1.f + e);
}

// ---------------- bf16 split helpers ----------------
__device__ __forceinline__ uint32_t pack2bf(float e0, float e1) {
    // reg.lo = bf16(e0), reg.hi = bf16(e1)
    uint32_t r;
    asm("cvt.rn.bf16x2.f32 %0, %1, %2;" : "=r"(r) : "f"(e1), "f"(e0));
    return r;
}
__device__ __forceinline__ float bfx2_lo_f(uint32_t p) { return __uint_as_float(p << 16); }
__device__ __forceinline__ float bfx2_hi_f(uint32_t p) { return __uint_as_float(p & 0xffff0000u); }

__device__ __forceinline__ void mma_bf16(float c[4], const uint32_t a[4], uint32_t b0, uint32_t b1) {
    asm volatile(
        "mma.sync.aligned.m16n8k16.row.col.f32.bf16.bf16.f32 "
        "{%0,%1,%2,%3}, {%4,%5,%6,%7}, {%8,%9}, {%0,%1,%2,%3};"
        : "+f"(c[0]), "+f"(c[1]), "+f"(c[2]), "+f"(c[3])
        : "r"(a[0]), "r"(a[1]), "r"(a[2]), "r"(a[3]), "r"(b0), "r"(b1));
}

// ---------------- order-preserving float<->key ----------------
__device__ __forceinline__ uint32_t f2key(float f) {
    uint32_t u = __float_as_uint(f);
    return (u & 0x80000000u) ? ~u : (u | 0x80000000u);
}
__device__ __forceinline__ float key2f(uint32_t k) {
    return __uint_as_float((k & 0x80000000u) ? (k ^ 0x80000000u) : ~k);
}

// ---------------- weight split prep: w[oc][ic][t] -> wH/wL[t][oc][icp] ----------------
__global__ void prepW(const float* __restrict__ w, uint32_t* __restrict__ wH,
                      uint32_t* __restrict__ wL, int IC) {
    int ICP = IC >> 1;
    int idx = blockIdx.x * 256 + threadIdx.x;
    if (idx >= 9 * 512 * ICP) return;
    int icp = idx % ICP;
    int rem = idx / ICP;
    int oc = rem % 512;
    int t = rem / 512;
    float f0 = w[((size_t)oc * IC + 2 * icp) * 9 + t];
    float f1 = w[((size_t)oc * IC + 2 * icp + 1) * 9 + t];
    uint32_t hi = pack2bf(f0, f1);
    uint32_t lo = pack2bf(f0 - bfx2_lo_f(hi), f1 - bfx2_hi_f(hi));
    wH[idx] = hi;
    wL[idx] = lo;
}

// ---------------- GEMM: C[m,n] = sum_k A[m,k] * W[n,k], optional relu ----------------
__global__ void gemm_nt(const float* __restrict__ A, const float* __restrict__ W,
                        float* __restrict__ C, int K, int N, int relu) {
    __shared__ float As[16][17], Ws[16][17];
    int tx = threadIdx.x, ty = threadIdx.y;
    int m = blockIdx.y * 16 + ty;
    int n0 = blockIdx.x * 16;
    float acc = 0.f;
    for (int k0 = 0; k0 < K; k0 += 16) {
        As[ty][tx] = A[m * K + k0 + tx];
        Ws[ty][tx] = W[(n0 + ty) * K + k0 + tx];
        __syncthreads();
#pragma unroll
        for (int kk = 0; kk < 16; kk++) acc = fmaf(As[ty][kk], Ws[tx][kk], acc);
        __syncthreads();
    }
    C[m * N + n0 + tx] = relu ? fmaxf(acc, 0.f) : acc;
}

// ---------------- 3x3 SAME conv via implicit GEMM on tensor cores ----------------
// grid (OC/64, B), block 256 (8 warps = 4 oc-groups x 2 pos-halves)
// pre-split bf16 hi/lo data staged packed in SMEM; inner loop = LDS + 3 MMAs.
template<int ICP, bool RELU>   // ICP = IC/2
__global__ void __launch_bounds__(256, 2) conv3x3_mma(const float* __restrict__ in,
                                                      const uint32_t* __restrict__ wH,
                                                      const uint32_t* __restrict__ wL,
                                                      float* __restrict__ out) {
    __shared__ uint32_t planeH[16][292], planeL[16][292];  // [icpair][18x16 cells + pad]
    __shared__ uint32_t wshH[16][68], wshL[16][68];        // [icpair][oc] pad->conflict-free

    const int b = blockIdx.y;
    const int oc0 = blockIdx.x * 64;
    const int tid = threadIdx.x;
    const int warp = tid >> 5, lane = tid & 31;
    const int gid = lane >> 2, tig = lane & 3;
    const int oc_w = (warp >> 1) * 16;
    const int pos_off = (warp & 1) * 104;

    // zero planes (halo + overflow stay zero; bf16x2 of 0 is 0)
    for (int e = tid; e < 16 * 292; e += 256) {
        ((uint32_t*)planeH)[e] = 0u;
        ((uint32_t*)planeL)[e] = 0u;
    }

    // per-lane center cells for the 13 n-tiles (n index = gid)
    int base[13];
#pragma unroll
    for (int pt = 0; pt < 13; pt++) {
        int p = pos_off + pt * 8 + gid;
        base[pt] = (p < HWD) ? ((p / 14) + 1) * 16 + (p % 14) + 1 : 273;
    }

    float C[13][4];
#pragma unroll
    for (int pt = 0; pt < 13; pt++) {
#pragma unroll
        for (int r = 0; r < 4; r++) C[pt][r] = 0.f;
    }

    const float* inb = in + (size_t)b * (2 * ICP) * HWD;

    for (int icp0 = 0; icp0 < ICP; icp0 += 16) {
        __syncthreads();   // previous chunk's compute done before plane overwrite
        for (int e = tid; e < 16 * HWD; e += 256) {
            int i = e / HWD, p = e % HWD;
            float f0 = inb[(2 * (icp0 + i)) * HWD + p];
            float f1 = inb[(2 * (icp0 + i) + 1) * HWD + p];
            uint32_t hi = pack2bf(f0, f1);
            uint32_t lo = pack2bf(f0 - bfx2_lo_f(hi), f1 - bfx2_hi_f(hi));
            int cell = ((p / 14) + 1) * 16 + (p % 14) + 1;
            planeH[i][cell] = hi;
            planeL[i][cell] = lo;
        }
        for (int t = 0; t < 9; t++) {
            __syncthreads();  // plane ready (t=0) / previous tap's compute done
            for (int e = tid; e < 1024; e += 256) {
                int i = e & 15, o = e >> 4;
                size_t off = ((size_t)(t * 512 + oc0 + o)) * ICP + icp0 + i;
                wshH[i][o] = wH[off];
                wshL[i][o] = wL[off];
            }
            __syncthreads();  // wsh ready
            // SAME conv: tap (dy,dx) reads in(y+dy-1, x+dx-1)
            const int toff = (t / 3 - 1) * 16 + (t % 3 - 1);
#pragma unroll
            for (int ks = 0; ks < 2; ks++) {
                const int kp = ks * 8;
                uint32_t ahi[4], alo[4];
                ahi[0] = wshH[kp + tig    ][oc_w + gid];
                ahi[1] = wshH[kp + tig    ][oc_w + gid + 8];
                ahi[2] = wshH[kp + 4 + tig][oc_w + gid];
                ahi[3] = wshH[kp + 4 + tig][oc_w + gid + 8];
                alo[0] = wshL[kp + tig    ][oc_w + gid];
                alo[1] = wshL[kp + tig    ][oc_w + gid + 8];
                alo[2] = wshL[kp + 4 + tig][oc_w + gid];
                alo[3] = wshL[kp + 4 + tig][oc_w + gid + 8];
#pragma unroll
                for (int pt = 0; pt < 13; pt++) {
                    const int pc = base[pt] + toff;
                    uint32_t b0h = planeH[kp + tig    ][pc];
                    uint32_t b1h = planeH[kp + 4 + tig][pc];
                    uint32_t b0l = planeL[kp + tig    ][pc];
                    uint32_t b1l = planeL[kp + 4 + tig][pc];
                    mma_bf16(C[pt], ahi, b0h, b1h);
                    mma_bf16(C[pt], alo, b0h, b1h);
                    mma_bf16(C[pt], ahi, b0l, b1l);
                }
            }
        }
    }

    // store: C rows = oc (gid, gid+8), cols = pos (tig*2, tig*2+1)
    float* ob = out + ((size_t)b * CD + oc0 + oc_w) * HWD;
#pragma unroll
    for (int pt = 0; pt < 13; pt++) {
        int p = pos_off + pt * 8 + tig * 2;
        if (p < HWD) {
            float v0 = C[pt][0], v2 = C[pt][2];
            if (RELU) { v0 = fmaxf(v0, 0.f); v2 = fmaxf(v2, 0.f); }
            ob[gid * HWD + p] = v0;
            ob[(gid + 8) * HWD + p] = v2;
        }
        if (p + 1 < HWD) {
            float v1 = C[pt][1], v3 = C[pt][3];
            if (RELU) { v1 = fmaxf(v1, 0.f); v3 = fmaxf(v3, 0.f); }
            ob[gid * HWD + p + 1] = v1;
            ob[(gid + 8) * HWD + p + 1] = v3;
        }
    }
}

// ---------------- masked mean pooling -> ind_vec ----------------
__global__ void indvec_kernel(const float* __restrict__ fv, const int* __restrict__ masks,
                              float* __restrict__ ind) {
    int b = blockIdx.x;
    int tid = threadIdx.x;
    __shared__ float m_s[HWD];
    __shared__ float red[8];
    float mv = 0.f;
    if (tid < HWD) { mv = (float)masks[b * HWD + tid]; m_s[tid] = mv; }
    float tot = blockReduceSum(mv, red);
    float inv_m = 1.f / tot;
    int lane = tid & 31, wid = tid >> 5;
    for (int c = wid; c < CD; c += 8) {
        const float* rowp = fv + ((size_t)b * CD + c) * HWD;
        float s = 0.f;
        for (int p = lane; p < HWD; p += 32) s += rowp[p] * m_s[p];
        s = warpReduceSum(s);
        if (lane == 0) ind[b * CD + c] = s * inv_m;
    }
}

// ---------------- per (b,p) inverse channel L2 norm ----------------
__global__ void invrho_kernel(const float* __restrict__ fv, float* __restrict__ invrho) {
    int b = blockIdx.x;
    int p = threadIdx.x;
    const float* base = fv + (size_t)b * CD * HWD + p;
    float s = 0.f;
    for (int c = 0; c < CD; c++) { float v = base[c * HWD]; s = fmaf(v, v, s); }
    invrho[b * HWD + p] = 1.f / fmaxf(sqrtf(s), 1e-12f);
}

// ---------------- normalize ind_vec -> ivn (+ transposed copy) ----------------
__global__ void ivn_kernel(const float* __restrict__ ind, float* __restrict__ ivn,
                           float* __restrict__ ivnT) {
    int b = blockIdx.x, c = threadIdx.x;
    __shared__ float red[16];
    float v = ind[b * CD + c];
    float ss = blockReduceSum(v * v, red);
    float o = v / fmaxf(sqrtf(ss), 1e-12f);
    ivn[b * CD + c] = o;
    ivnT[c * BB + b] = o;
}

// ---------------- transpose fa ----------------
__global__ void transpose_fa(const float* __restrict__ fa, float* __restrict__ faT) {
    int idx = blockIdx.x * 256 + threadIdx.x;
    int b = idx >> 9, c = idx & 511;
    faT[c * BB + b] = fa[idx];
}

// ---------------- Sij[i,j,p] = <ivn[j], fv[i,:,p]> * invrho[i,p] ----------------
__global__ void sij_gemm(const float* __restrict__ ivn, const float* __restrict__ fv,
                         const float* __restrict__ invrho, float* __restrict__ Sij) {
    int i = blockIdx.z;
    int p0 = blockIdx.x * 64;
    int j0 = blockIdx.y * 64;
    __shared__ float As[64][17];
    __shared__ float Bs[16][65];
    int tid = threadIdx.y * 16 + threadIdx.x;
    float acc[4][4] = {};
    const float* fvi = fv + (size_t)i * CD * HWD;
    for (int k0 = 0; k0 < CD; k0 += 16) {
#pragma unroll
        for (int r = 0; r < 4; r++) {
            int e = tid + r * 256;
            int row = e >> 4, col = e & 15;
            As[row][col] = ivn[(j0 + row) * CD + k0 + col];
        }
#pragma unroll
        for (int r = 0; r < 4; r++) {
            int e = tid + r * 256;
            int row = e >> 6, col = e & 63;
            int p = p0 + col;
            Bs[row][col] = (p < HWD) ? fvi[(k0 + row) * HWD + p] : 0.f;
        }
        __syncthreads();
#pragma unroll
        for (int kk = 0; kk < 16; kk++) {
            float a[4], bb[4];
#pragma unroll
            for (int r = 0; r < 4; r++) a[r] = As[threadIdx.y * 4 + r][kk];
#pragma unroll
            for (int c = 0; c < 4; c++) bb[c] = Bs[kk][threadIdx.x * 4 + c];
#pragma unroll
            for (int r = 0; r < 4; r++)
#pragma unroll
                for (int c = 0; c < 4; c++)
                    acc[r][c] = fmaf(a[r], bb[c], acc[r][c]);
        }
        __syncthreads();
    }
#pragma unroll
    for (int r = 0; r < 4; r++) {
        int j = j0 + threadIdx.y * 4 + r;
#pragma unroll
        for (int c = 0; c < 4; c++) {
            int p = p0 + threadIdx.x * 4 + c;
            if (p < HWD)
                Sij[((size_t)(i * BB + j)) * HWD + p] = acc[r][c] * invrho[i * HWD + p];
        }
    }
}

// ---------------- warp-per-row dual radix-select + soft-mask pooling ----------------
// thresholds: 19th largest (pos), 99th largest = 98th smallest (neg). Exact.
__global__ void topk_radix(const float* __restrict__ Sij, float* __restrict__ SP,
                           float* __restrict__ SN) {
    int row = (blockIdx.x * blockDim.x + threadIdx.x) >> 5;   // (i*256 + j)
    int lane = threadIdx.x & 31;
    const float* rp = Sij + (size_t)row * HWD;

    float v[7];
    uint32_t key[7];
#pragma unroll
    for (int e = 0; e < 7; e++) {
        int p = e * 32 + lane;
        bool valid = (p < HWD);
        v[e] = valid ? rp[p] : 0.f;
        key[e] = valid ? f2key(v[e]) : 0u;   // real keys are >= 0x007FFFFF, 0 never selected
    }

    uint32_t p1 = 0, p2 = 0;   // prefixes for k=19 (pos) and k=99 (neg)
#pragma unroll
    for (int b = 31; b >= 0; b--) {
        uint32_t c1 = (p1 >> b) | 1u;
        uint32_t c2 = (p2 >> b) | 1u;
        int n = 0;
#pragma unroll
        for (int e = 0; e < 7; e++) {
            uint32_t t = key[e] >> b;
            n += (t >= c1) ? 1 : 0;
            n += (t >= c2) ? 0x10000 : 0;
        }
        n = __reduce_add_sync(0xffffffffu, n);
        if ((n & 0xffff) >= 19) p1 |= (1u << b);
        if ((n >> 16) >= 99)    p2 |= (1u << b);
    }
    float pthr = key2f(p1);
    float nthr = key2f(p2);

    float svp = 0.f, sp = 0.f, svn = 0.f, sn = 0.f;
#pragma unroll
    for (int e = 0; e < 7; e++) {
        int p = e * 32 + lane;
        if (p < HWD) {
            float mp = sigmoidf_stable((v[e] - pthr) * TS_INV);
            float mn = 1.f - sigmoidf_stable((v[e] - nthr) * TS_INV);
            svp += v[e] * mp; sp += mp;
            svn += v[e] * mn; sn += mn;
        }
    }
    svp = warpReduceSum(svp); sp = warpReduceSum(sp);
    svn = warpReduceSum(svn); sn = warpReduceSum(sn);
    if (lane == 0) {
        SP[row] = svp / sp;
        SN[row] = svn / sn;
    }
}

// ---------------- contrastive losses ----------------
__global__ void loss12_kernel(const float* __restrict__ SP, const float* __restrict__ SN,
                              float* __restrict__ l1, float* __restrict__ l2) {
    int i = blockIdx.x, j = threadIdx.x;
    __shared__ float red[8];
    float a1 = SP[i * BB + j] * TC_INV, a2 = SN[i * BB + j] * TC_INV;
    float b1 = SP[j * BB + i] * TC_INV, b2 = SN[j * BB + i] * TC_INV;
    float m1 = blockReduceMax(fmaxf(a1, a2), red);
    float s1 = blockReduceSum(expf(a1 - m1) + expf(a2 - m1), red);
    float m2 = blockReduceMax(fmaxf(b1, b2), red);
    float s2 = blockReduceSum(expf(b1 - m2) + expf(b2 - m2), red);
    if (j == 0) {
        float diag = SP[i * BB + i] * TC_INV;
        l1[i] = logf(s1) + m1 - diag;
        l2[i] = logf(s2) + m2 - diag;
    }
}

// ---------------- weighted pairwise-distance matrix E ----------------
__global__ void dist_kernel(const float* __restrict__ ind, const float* __restrict__ ivn,
                            const float* __restrict__ faT, const float* __restrict__ ivnT,
                            float* __restrict__ E) {
    int i = blockIdx.x, j = threadIdx.x;
    __shared__ float ind_s[CD], ivn_s[CD];
    for (int c = j; c < CD; c += 256) { ind_s[c] = ind[i * CD + c]; ivn_s[c] = ivn[i * CD + c]; }
    __syncthreads();
    float d = 0.f, vv = 0.f;
    for (int c = 0; c < CD; c++) {
        float t = ind_s[c] - faT[c * BB + j] + 1e-6f;
        d = fmaf(t, t, d);
        vv = fmaf(ivn_s[c], ivnT[c * BB + j], vv);
    }
    E[i * BB + j] = (i == j) ? d : d * vv * (1.f / 255.f);
}

// ---------------- final scalar losses ----------------
__global__ void final_kernel(const float* __restrict__ E, const float* __restrict__ l1,
                             const float* __restrict__ l2, float* __restrict__ out) {
    int t = threadIdx.x;   // 256
    __shared__ float red[8];
    float r = 0.f, c = 0.f;
    for (int j = 0; j < BB; j++) r += E[t * BB + j];
    for (int i2 = 0; i2 < BB; i2++) c += E[i2 * BB + t];
    float a3 = fmaxf(r + 0.6f, 0.f);
    float a4 = fmaxf(c + 0.6f, 0.f);
    float s3 = blockReduceSum(a3, red);
    float s4 = blockReduceSum(a4, red);
    float s1 = blockReduceSum(l1[t], red);
    float s2 = blockReduceSum(l2[t], red);
    if (t == 0) {
        out[0] = (s1 + s2) * (0.5f / (float)BB);
        out[1] = (s3 + s4) * (0.5f / (float)BB);
    }
}

// ---------------- launch ----------------
extern "C" void kernel_launch(void* const* d_in, const int* in_sizes, int n_in,
                              void* d_out, int out_size) {
    const float* ev   = (const float*)d_in[0];
    const float* ea   = (const float*)d_in[1];
    const int*   masks= (const int*)  d_in[2];
    const float* Wfc1 = (const float*)d_in[3];
    const float* Wfc2 = (const float*)d_in[4];
    const float* Wc1  = (const float*)d_in[5];
    const float* Wc2  = (const float*)d_in[6];
    float* out = (float*)d_out;

    float *hfc, *fa, *faT, *h1, *fv, *ind, *ivn, *ivnT, *invrho, *Sij, *SP, *SN, *E, *l1, *l2;
    uint32_t *wH1, *wL1, *wH2, *wL2;
    cudaGetSymbolAddress((void**)&hfc,    d_hfc);
    cudaGetSymbolAddress((void**)&fa,     d_fa);
    cudaGetSymbolAddress((void**)&faT,    d_faT);
    cudaGetSymbolAddress((void**)&h1,     d_h1);
    cudaGetSymbolAddress((void**)&fv,     d_fv);
    cudaGetSymbolAddress((void**)&ind,    d_ind);
    cudaGetSymbolAddress((void**)&ivn,    d_ivn);
    cudaGetSymbolAddress((void**)&ivnT,   d_ivnT);
    cudaGetSymbolAddress((void**)&invrho, d_invrho);
    cudaGetSymbolAddress((void**)&Sij,    d_Sij);
    cudaGetSymbolAddress((void**)&SP,     d_SP);
    cudaGetSymbolAddress((void**)&SN,     d_SN);
    cudaGetSymbolAddress((void**)&E,      d_E);
    cudaGetSymbolAddress((void**)&l1,     d_l1);
    cudaGetSymbolAddress((void**)&l2,     d_l2);
    cudaGetSymbolAddress((void**)&wH1,    d_wH1);
    cudaGetSymbolAddress((void**)&wL1,    d_wL1);
    cudaGetSymbolAddress((void**)&wH2,    d_wH2);
    cudaGetSymbolAddress((void**)&wL2,    d_wL2);

    // audio branch
    gemm_nt<<<dim3(CD / 16, BB / 16), dim3(16, 16)>>>(ea, Wfc1, hfc, 2048, CD, 1);
    gemm_nt<<<dim3(CD / 16, BB / 16), dim3(16, 16)>>>(hfc, Wfc2, fa, CD, CD, 0);
    transpose_fa<<<512, 256>>>(fa, faT);

    // pre-split packed weights for implicit-GEMM convs
    prepW<<<(9 * 512 * 192 + 255) / 256, 256>>>(Wc1, wH1, wL1, 384);
    prepW<<<(9 * 512 * 256 + 255) / 256, 256>>>(Wc2, wH2, wL2, 512);

    // visual branch (tensor-core convs)
    conv3x3_mma<192, true ><<<dim3(CD / 64, BB), 256>>>(ev, wH1, wL1, h1);
    conv3x3_mma<256, false><<<dim3(CD / 64, BB), 256>>>(h1, wH2, wL2, fv);

    indvec_kernel<<<BB, 256>>>(fv, masks, ind);
    invrho_kernel<<<BB, HWD>>>(fv, invrho);
    ivn_kernel<<<BB, CD>>>(ind, ivn, ivnT);

    // similarity tensor + exact top-k soft pooling
    sij_gemm<<<dim3(4, 4, BB), dim3(16, 16)>>>(ivn, fv, invrho, Sij);
    topk_radix<<<(BB * BB) / 8, 256>>>(Sij, SP, SN);

    // losses
    loss12_kernel<<<BB, 256>>>(SP, SN, l1, l2);
    dist_kernel<<<BB, 256>>>(ind, ivn, faT, ivnT, E);
    final_kernel<<<1, 256>>>(E, l1, l2, out);
}

// round 11
// speedup vs baseline: 1.6478x; 1.6478x over previous
#include <cuda_runtime.h>
#include <cuda_fp16.h>
#include <math.h>
#include <stdint.h>

// ---------------- problem constants ----------------
#define BB 256
#define HWD 196      // 14*14
#define CD 512
#define NT 49        // 7x7 winograd tiles per image
#define MW (BB*NT)   // 12544 winograd GEMM M
#define TS_INV (1.0f/0.03f)
#define TC_INV (1.0f/0.07f)

// ---------------- scratch (device globals; no runtime allocation) ----------------
__device__ float d_hfc[BB*CD];
__device__ float d_fa[BB*CD];
__device__ float d_faT[CD*BB];
__device__ float d_h1[BB*HWD*CD];     // relu(conv1), layout [b][p][c]
__device__ float d_fv[BB*HWD*CD];     // conv2 out,    layout [b][p][c]
__device__ float d_ind[BB*CD];
__device__ float d_ivn[BB*CD];
__device__ float d_ivnT[CD*BB];
__device__ float d_invrho[BB*HWD];
__device__ float d_Sij[BB*BB*HWD];
__device__ float d_SP[BB*BB];
__device__ float d_SN[BB*BB];
__device__ float d_E[BB*BB];
__device__ float d_l1[BB];
__device__ float d_l2[BB];
// winograd buffers (V/M reused by both convs)
__device__ __half d_Vh[16*MW*CD];     // 205.6 MB
__device__ __half d_Vl[16*MW*CD];
__device__ float  d_M [(size_t)16*MW*CD];  // 411 MB
__device__ __half d_U1h[16*512*384], d_U1l[16*512*384];
__device__ __half d_U2h[16*512*512], d_U2l[16*512*512];

// ---------------- reduction helpers ----------------
__device__ __forceinline__ float warpReduceSum(float v) {
#pragma unroll
    for (int o = 16; o > 0; o >>= 1) v += __shfl_xor_sync(0xffffffffu, v, o);
    return v;
}
__device__ __forceinline__ float warpReduceMax(float v) {
#pragma unroll
    for (int o = 16; o > 0; o >>= 1) v = fmaxf(v, __shfl_xor_sync(0xffffffffu, v, o));
    return v;
}
__device__ __forceinline__ float blockReduceSum(float v, float* red) {
    __syncthreads();
    int lane = threadIdx.x & 31, wid = threadIdx.x >> 5;
    v = warpReduceSum(v);
    if (lane == 0) red[wid] = v;
    __syncthreads();
    int nw = (blockDim.x + 31) >> 5;
    if (wid == 0) {
        float r = (threadIdx.x < nw) ? red[threadIdx.x] : 0.f;
        r = warpReduceSum(r);
        if (lane == 0) red[0] = r;
    }
    __syncthreads();
    return red[0];
}
__device__ __forceinline__ float blockReduceMax(float v, float* red) {
    __syncthreads();
    int lane = threadIdx.x & 31, wid = threadIdx.x >> 5;
    v = warpReduceMax(v);
    if (lane == 0) red[wid] = v;
    __syncthreads();
    int nw = (blockDim.x + 31) >> 5;
    if (wid == 0) {
        float r = (threadIdx.x < nw) ? red[threadIdx.x] : -INFINITY;
        r = warpReduceMax(r);
        if (lane == 0) red[0] = r;
    }
    __syncthreads();
    return red[0];
}

__device__ __forceinline__ float sigmoidf_stable(float x) {
    if (x >= 0.f) { float e = expf(-x); return 1.f / (1.f + e); }
    float e = expf(x); return e / (1.f + e);
}

// ---------------- fp16 mma m16n8k16 ----------------
__device__ __forceinline__ void mma_f16(float c[4], const uint32_t a[4], uint32_t b0, uint32_t b1) {
    asm volatile(
        "mma.sync.aligned.m16n8k16.row.col.f32.f16.f16.f32 "
        "{%0,%1,%2,%3}, {%4,%5,%6,%7}, {%8,%9}, {%0,%1,%2,%3};"
        : "+f"(c[0]), "+f"(c[1]), "+f"(c[2]), "+f"(c[3])
        : "r"(a[0]), "r"(a[1]), "r"(a[2]), "r"(a[3]), "r"(b0), "r"(b1));
}

// ---------------- order-preserving float<->key ----------------
__device__ __forceinline__ uint32_t f2key(float f) {
    uint32_t u = __float_as_uint(f);
    return (u & 0x80000000u) ? ~u : (u | 0x80000000u);
}
__device__ __forceinline__ float key2f(uint32_t k) {
    return __uint_as_float((k & 0x80000000u) ? (k ^ 0x80000000u) : ~k);
}

// ---------------- winograd split-store helper ----------------
__device__ __forceinline__ void split_store(float v, __half* ph, __half* pl) {
    __half h = __float2half_rn(v);
    *ph = h;
    *pl = __float2half_rn(v - __half2float(h));
}

// ---------------- weight transform: U = G g G^T, per (oc, ic) ----------------
// w layout [oc][ic][3][3]; U layout [k16][oc 512][ic IC]
__global__ void wino_wprep(const float* __restrict__ w, __half* __restrict__ Uh,
                           __half* __restrict__ Ul, int IC) {
    int idx = blockIdx.x * 256 + threadIdx.x;
    if (idx >= 512 * IC) return;
    int oc = idx / IC, ic = idx % IC;
    float g[3][3];
#pragma unroll
    for (int r = 0; r < 3; r++)
#pragma unroll
        for (int c = 0; c < 3; c++) g[r][c] = w[((size_t)idx) * 9 + r * 3 + c];
    float t[4][3];
#pragma unroll
    for (int c = 0; c < 3; c++) {
        t[0][c] = g[0][c];
        t[1][c] = 0.5f * (g[0][c] + g[1][c] + g[2][c]);
        t[2][c] = 0.5f * (g[0][c] - g[1][c] + g[2][c]);
        t[3][c] = g[2][c];
    }
#pragma unroll
    for (int r = 0; r < 4; r++) {
        float u0 = t[r][0];
        float u1 = 0.5f * (t[r][0] + t[r][1] + t[r][2]);
        float u2 = 0.5f * (t[r][0] - t[r][1] + t[r][2]);
        float u3 = t[r][2];
        float uu[4] = {u0, u1, u2, u3};
#pragma unroll
        for (int c = 0; c < 4; c++) {
            size_t off = ((size_t)(r * 4 + c) * 512 + oc) * IC + ic;
            split_store(uu[c], Uh + off, Ul + off);
        }
    }
}

// ---------------- input transform V = B^T d B ----------------
__device__ __forceinline__ void wino_Vcalc(const float d[4][4], float V[16]) {
    float t[4][4];
#pragma unroll
    for (int c = 0; c < 4; c++) {
        t[0][c] = d[0][c] - d[2][c];
        t[1][c] = d[1][c] + d[2][c];
        t[2][c] = d[2][c] - d[1][c];
        t[3][c] = d[1][c] - d[3][c];
    }
#pragma unroll
    for (int r = 0; r < 4; r++) {
        V[r * 4 + 0] = t[r][0] - t[r][2];
        V[r * 4 + 1] = t[r][1] + t[r][2];
        V[r * 4 + 2] = t[r][2] - t[r][1];
        V[r * 4 + 3] = t[r][1] - t[r][3];
    }
}

// input in NCHW (ev): grid (256 b, IC/8), block 256; smem 8 planes
__global__ void wino_inprep_nchw(const float* __restrict__ in, __half* __restrict__ Vh,
                                 __half* __restrict__ Vl, int IC) {
    __shared__ float plane[8][HWD];
    int b = blockIdx.x;
    int ic0 = blockIdx.y * 8;
    for (int e = threadIdx.x; e < 8 * HWD; e += 256) {
        int ic = e / HWD, p = e % HWD;
        plane[ic][p] = in[((size_t)b * IC + ic0 + ic) * HWD + p];
    }
    __syncthreads();
    for (int e = threadIdx.x; e < 8 * NT; e += 256) {
        int ic = e & 7, t = e >> 3;
        int ty = t / 7, tx = t % 7;
        float d[4][4];
#pragma unroll
        for (int r = 0; r < 4; r++) {
            int iy = 2 * ty - 1 + r;
#pragma unroll
            for (int c = 0; c < 4; c++) {
                int ix = 2 * tx - 1 + c;
                d[r][c] = (iy >= 0 && iy < 14 && ix >= 0 && ix < 14) ? plane[ic][iy * 14 + ix] : 0.f;
            }
        }
        float V[16];
        wino_Vcalc(d, V);
        int m = b * NT + t;
#pragma unroll
        for (int k = 0; k < 16; k++) {
            size_t off = ((size_t)k * MW + m) * IC + ic0 + ic;
            split_store(V[k], Vh + off, Vl + off);
        }
    }
}

// input in [b][p][c] (h1): grid (256 b, 7 tchunk), block 256
__global__ void wino_inprep_pc(const float* __restrict__ in, __half* __restrict__ Vh,
                               __half* __restrict__ Vl) {
    int b = blockIdx.x;
    const float* ib = in + (size_t)b * HWD * CD;
    for (int e = threadIdx.x; e < 7 * CD; e += 256) {
        int ic = e & (CD - 1), tl = e >> 9;
        int t = blockIdx.y * 7 + tl;
        int ty = t / 7, tx = t % 7;
        float d[4][4];
#pragma unroll
        for (int r = 0; r < 4; r++) {
            int iy = 2 * ty - 1 + r;
#pragma unroll
            for (int c = 0; c < 4; c++) {
                int ix = 2 * tx - 1 + c;
                d[r][c] = (iy >= 0 && iy < 14 && ix >= 0 && ix < 14)
                          ? ib[(size_t)(iy * 14 + ix) * CD + ic] : 0.f;
            }
        }
        float V[16];
        wino_Vcalc(d, V);
        int m = b * NT + t;
#pragma unroll
        for (int k = 0; k < 16; k++) {
            size_t off = ((size_t)k * MW + m) * CD + ic;
            split_store(V[k], Vh + off, Vl + off);
        }
    }
}

// ---------------- winograd GEMM: M[k][m][oc] = sum_ic V[k][m][ic]*U[k][oc][ic] ----------------
// grid (8 octile, 98 mtile, 16 k), block 256 (8 warps = 4 ocgroups x 2 mhalves)
// fp16 hi/lo 3-MMA split; fragment conventions identical to R4's passing conv kernel.
template<int IC>
__global__ void __launch_bounds__(256) wino_gemm(const __half* __restrict__ Vh,
                                                 const __half* __restrict__ Vl,
                                                 const __half* __restrict__ Uh,
                                                 const __half* __restrict__ Ul,
                                                 float* __restrict__ Mout) {
    __shared__ uint32_t Ush[16][72], Usl[16][72];   // [icpair][oc64]
    __shared__ uint32_t Vsh[16][136], Vsl[16][136]; // [icpair][m128]

    const int oc0 = blockIdx.x * 64;
    const int m0 = blockIdx.y * 128;
    const int k = blockIdx.z;
    const int tid = threadIdx.x;
    const int warp = tid >> 5, lane = tid & 31;
    const int gid = lane >> 2, tig = lane & 3;
    const int ocw = (warp >> 1) * 16;
    const int mhalf = (warp & 1) * 64;

    float C[8][4];
#pragma unroll
    for (int mt = 0; mt < 8; mt++)
#pragma unroll
        for (int r = 0; r < 4; r++) C[mt][r] = 0.f;

    const __half* Ukh = Uh + (size_t)k * 512 * IC;
    const __half* Ukl = Ul + (size_t)k * 512 * IC;
    const __half* Vkh = Vh + (size_t)k * MW * IC;
    const __half* Vkl = Vl + (size_t)k * MW * IC;

    for (int ic0 = 0; ic0 < IC; ic0 += 32) {
        __syncthreads();
        for (int e = tid; e < 1024; e += 256) {
            int pr = e & 15, o = e >> 4;
            size_t off = (size_t)(oc0 + o) * IC + ic0 + 2 * pr;
            Ush[pr][o] = *(const uint32_t*)(Ukh + off);
            Usl[pr][o] = *(const uint32_t*)(Ukl + off);
        }
        for (int e = tid; e < 2048; e += 256) {
            int pr = e & 15, m = e >> 4;
            size_t off = (size_t)(m0 + m) * IC + ic0 + 2 * pr;
            Vsh[pr][m] = *(const uint32_t*)(Vkh + off);
            Vsl[pr][m] = *(const uint32_t*)(Vkl + off);
        }
        __syncthreads();
#pragma unroll
        for (int ks = 0; ks < 2; ks++) {
            const int kp = ks * 8;
            uint32_t ahi[4], alo[4];
            ahi[0] = Ush[kp + tig][ocw + gid];
            ahi[1] = Ush[kp + tig][ocw + gid + 8];
            ahi[2] = Ush[kp + 4 + tig][ocw + gid];
            ahi[3] = Ush[kp + 4 + tig][ocw + gid + 8];
            alo[0] = Usl[kp + tig][ocw + gid];
            alo[1] = Usl[kp + tig][ocw + gid + 8];
            alo[2] = Usl[kp + 4 + tig][ocw + gid];
            alo[3] = Usl[kp + 4 + tig][ocw + gid + 8];
#pragma unroll
            for (int mt = 0; mt < 8; mt++) {
                const int mc = mhalf + mt * 8 + gid;
                uint32_t b0h = Vsh[kp + tig][mc];
                uint32_t b1h = Vsh[kp + 4 + tig][mc];
                uint32_t b0l = Vsl[kp + tig][mc];
                uint32_t b1l = Vsl[kp + 4 + tig][mc];
                mma_f16(C[mt], ahi, b0h, b1h);
                mma_f16(C[mt], alo, b0h, b1h);
                mma_f16(C[mt], ahi, b0l, b1l);
            }
        }
    }

    // store: D row = oc (gid), col = m (tig*2, tig*2+1); rows +8 in c2/c3
    float* Mk = Mout + (size_t)k * MW * 512;
#pragma unroll
    for (int mt = 0; mt < 8; mt++) {
        int m = m0 + mhalf + mt * 8 + tig * 2;
        int oc = oc0 + ocw + gid;
        float* mp = Mk + (size_t)m * 512 + oc;
        mp[0] = C[mt][0];
        mp[512] = C[mt][1];
        mp[8] = C[mt][2];
        mp[512 + 8] = C[mt][3];
    }
}

// ---------------- output inverse transform: Y = A^T M A -> out[b][p][c] ----------------
template<bool RELU>
__global__ void wino_out(const float* __restrict__ Min, float* __restrict__ out) {
    int b = blockIdx.x, t = blockIdx.y;
    int oc = threadIdx.x;   // 512
    int m = b * NT + t;
    float M[16];
#pragma unroll
    for (int k = 0; k < 16; k++) M[k] = Min[((size_t)k * MW + m) * 512 + oc];
    float tr[2][4];
#pragma unroll
    for (int c = 0; c < 4; c++) {
        tr[0][c] = M[0 * 4 + c] + M[1 * 4 + c] + M[2 * 4 + c];
        tr[1][c] = M[1 * 4 + c] - M[2 * 4 + c] - M[3 * 4 + c];
    }
    int ty = t / 7, tx = t % 7;
    float* ob = out + (size_t)b * HWD * CD + oc;
#pragma unroll
    for (int r = 0; r < 2; r++) {
        float y0 = tr[r][0] + tr[r][1] + tr[r][2];
        float y1 = tr[r][1] - tr[r][2] - tr[r][3];
        if (RELU) { y0 = fmaxf(y0, 0.f); y1 = fmaxf(y1, 0.f); }
        int p = (2 * ty + r) * 14 + 2 * tx;
        ob[(size_t)p * CD] = y0;
        ob[(size_t)(p + 1) * CD] = y1;
    }
}

// ---------------- GEMM: C[m,n] = sum_k A[m,k] * W[n,k], optional relu ----------------
__global__ void gemm_nt(const float* __restrict__ A, const float* __restrict__ W,
                        float* __restrict__ C, int K, int N, int relu) {
    __shared__ float As[16][17], Ws[16][17];
    int tx = threadIdx.x, ty = threadIdx.y;
    int m = blockIdx.y * 16 + ty;
    int n0 = blockIdx.x * 16;
    float acc = 0.f;
    for (int k0 = 0; k0 < K; k0 += 16) {
        As[ty][tx] = A[m * K + k0 + tx];
        Ws[ty][tx] = W[(n0 + ty) * K + k0 + tx];
        __syncthreads();
#pragma unroll
        for (int kk = 0; kk < 16; kk++) acc = fmaf(As[ty][kk], Ws[tx][kk], acc);
        __syncthreads();
    }
    C[m * N + n0 + tx] = relu ? fmaxf(acc, 0.f) : acc;
}

// ---------------- masked mean pooling (fv [b][p][c]) -> ind_vec ----------------
__global__ void indvec_kernel(const float* __restrict__ fv, const int* __restrict__ masks,
                              float* __restrict__ ind) {
    int b = blockIdx.x;
    int c = threadIdx.x;   // 512
    __shared__ float m_s[HWD];
    __shared__ float red[16];
    float mv = 0.f;
    if (c < HWD) { mv = (float)masks[b * HWD + c]; m_s[c] = mv; }
    float tot = blockReduceSum(mv, red);
    float inv_m = 1.f / tot;
    const float* fb = fv + (size_t)b * HWD * CD + c;
    float s = 0.f;
    for (int p = 0; p < HWD; p++) s = fmaf(fb[(size_t)p * CD], m_s[p], s);
    ind[b * CD + c] = s * inv_m;
}

// ---------------- per (b,p) inverse channel L2 norm (fv [b][p][c]) ----------------
__global__ void invrho_kernel(const float* __restrict__ fv, float* __restrict__ invrho) {
    int b = blockIdx.x;
    int lane = threadIdx.x & 31, w = threadIdx.x >> 5;  // 8 warps
    for (int p = w; p < HWD; p += 8) {
        const float* row = fv + ((size_t)b * HWD + p) * CD;
        float s = 0.f;
        for (int c = lane; c < CD; c += 32) { float v = row[c]; s = fmaf(v, v, s); }
        s = warpReduceSum(s);
        if (lane == 0) invrho[b * HWD + p] = 1.f / fmaxf(sqrtf(s), 1e-12f);
    }
}

// ---------------- normalize ind_vec -> ivn (+ transposed copy) ----------------
__global__ void ivn_kernel(const float* __restrict__ ind, float* __restrict__ ivn,
                           float* __restrict__ ivnT) {
    int b = blockIdx.x, c = threadIdx.x;
    __shared__ float red[16];
    float v = ind[b * CD + c];
    float ss = blockReduceSum(v * v, red);
    float o = v / fmaxf(sqrtf(ss), 1e-12f);
    ivn[b * CD + c] = o;
    ivnT[c * BB + b] = o;
}

// ---------------- transpose fa ----------------
__global__ void transpose_fa(const float* __restrict__ fa, float* __restrict__ faT) {
    int idx = blockIdx.x * 256 + threadIdx.x;
    int b = idx >> 9, c = idx & 511;
    faT[c * BB + b] = fa[idx];
}

// ---------------- Sij[i,j,p] = <ivn[j], fv[i,p,:]> * invrho[i,p] ----------------
__global__ void sij_gemm(const float* __restrict__ ivn, const float* __restrict__ fv,
                         const float* __restrict__ invrho, float* __restrict__ Sij) {
    int i = blockIdx.z;
    int p0 = blockIdx.x * 64;
    int j0 = blockIdx.y * 64;
    __shared__ float As[64][17];
    __shared__ float Bs[16][65];
    int tid = threadIdx.y * 16 + threadIdx.x;
    float acc[4][4] = {};
    const float* fvi = fv + (size_t)i * HWD * CD;
    for (int k0 = 0; k0 < CD; k0 += 16) {
#pragma unroll
        for (int r = 0; r < 4; r++) {
            int e = tid + r * 256;
            int row = e >> 4, col = e & 15;
            As[row][col] = ivn[(j0 + row) * CD + k0 + col];
        }
#pragma unroll
        for (int r = 0; r < 4; r++) {
            int e = tid + r * 256;
            int cs = e & 15, p = e >> 4;     // fv [p][c]: c fastest -> coalesced
            int pg = p0 + p;
            Bs[cs][p] = (pg < HWD) ? fvi[(size_t)pg * CD + k0 + cs] : 0.f;
        }
        __syncthreads();
#pragma unroll
        for (int kk = 0; kk < 16; kk++) {
            float a[4], bb[4];
#pragma unroll
            for (int r = 0; r < 4; r++) a[r] = As[threadIdx.y * 4 + r][kk];
#pragma unroll
            for (int c = 0; c < 4; c++) bb[c] = Bs[kk][threadIdx.x * 4 + c];
#pragma unroll
            for (int r = 0; r < 4; r++)
#pragma unroll
                for (int c = 0; c < 4; c++)
                    acc[r][c] = fmaf(a[r], bb[c], acc[r][c]);
        }
        __syncthreads();
    }
#pragma unroll
    for (int r = 0; r < 4; r++) {
        int j = j0 + threadIdx.y * 4 + r;
#pragma unroll
        for (int c = 0; c < 4; c++) {
            int p = p0 + threadIdx.x * 4 + c;
            if (p < HWD)
                Sij[((size_t)(i * BB + j)) * HWD + p] = acc[r][c] * invrho[i * HWD + p];
        }
    }
}

// ---------------- warp-per-row dual radix-select + soft-mask pooling ----------------
__global__ void topk_radix(const float* __restrict__ Sij, float* __restrict__ SP,
                           float* __restrict__ SN) {
    int row = (blockIdx.x * blockDim.x + threadIdx.x) >> 5;
    int lane = threadIdx.x & 31;
    const float* rp = Sij + (size_t)row * HWD;

    float v[7];
    uint32_t key[7];
#pragma unroll
    for (int e = 0; e < 7; e++) {
        int p = e * 32 + lane;
        bool valid = (p < HWD);
        v[e] = valid ? rp[p] : 0.f;
        key[e] = valid ? f2key(v[e]) : 0u;
    }

    uint32_t p1 = 0, p2 = 0;
#pragma unroll
    for (int b = 31; b >= 0; b--) {
        uint32_t c1 = (p1 >> b) | 1u;
        uint32_t c2 = (p2 >> b) | 1u;
        int n = 0;
#pragma unroll
        for (int e = 0; e < 7; e++) {
            uint32_t t = key[e] >> b;
            n += (t >= c1) ? 1 : 0;
            n += (t >= c2) ? 0x10000 : 0;
        }
        n = __reduce_add_sync(0xffffffffu, n);
        if ((n & 0xffff) >= 19) p1 |= (1u << b);
        if ((n >> 16) >= 99)    p2 |= (1u << b);
    }
    float pthr = key2f(p1);
    float nthr = key2f(p2);

    float svp = 0.f, sp = 0.f, svn = 0.f, sn = 0.f;
#pragma unroll
    for (int e = 0; e < 7; e++) {
        int p = e * 32 + lane;
        if (p < HWD) {
            float mp = sigmoidf_stable((v[e] - pthr) * TS_INV);
            float mn = 1.f - sigmoidf_stable((v[e] - nthr) * TS_INV);
            svp += v[e] * mp; sp += mp;
            svn += v[e] * mn; sn += mn;
        }
    }
    svp = warpReduceSum(svp); sp = warpReduceSum(sp);
    svn = warpReduceSum(svn); sn = warpReduceSum(sn);
    if (lane == 0) {
        SP[row] = svp / sp;
        SN[row] = svn / sn;
    }
}

// ---------------- contrastive losses ----------------
__global__ void loss12_kernel(const float* __restrict__ SP, const float* __restrict__ SN,
                              float* __restrict__ l1, float* __restrict__ l2) {
    int i = blockIdx.x, j = threadIdx.x;
    __shared__ float red[8];
    float a1 = SP[i * BB + j] * TC_INV, a2 = SN[i * BB + j] * TC_INV;
    float b1 = SP[j * BB + i] * TC_INV, b2 = SN[j * BB + i] * TC_INV;
    float m1 = blockReduceMax(fmaxf(a1, a2), red);
    float s1 = blockReduceSum(expf(a1 - m1) + expf(a2 - m1), red);
    float m2 = blockReduceMax(fmaxf(b1, b2), red);
    float s2 = blockReduceSum(expf(b1 - m2) + expf(b2 - m2), red);
    if (j == 0) {
        float diag = SP[i * BB + i] * TC_INV;
        l1[i] = logf(s1) + m1 - diag;
        l2[i] = logf(s2) + m2 - diag;
    }
}

// ---------------- weighted pairwise-distance matrix E ----------------
__global__ void dist_kernel(const float* __restrict__ ind, const float* __restrict__ ivn,
                            const float* __restrict__ faT, const float* __restrict__ ivnT,
                            float* __restrict__ E) {
    int i = blockIdx.x, j = threadIdx.x;
    __shared__ float ind_s[CD], ivn_s[CD];
    for (int c = j; c < CD; c += 256) { ind_s[c] = ind[i * CD + c]; ivn_s[c] = ivn[i * CD + c]; }
    __syncthreads();
    float d = 0.f, vv = 0.f;
    for (int c = 0; c < CD; c++) {
        float t = ind_s[c] - faT[c * BB + j] + 1e-6f;
        d = fmaf(t, t, d);
        vv = fmaf(ivn_s[c], ivnT[c * BB + j], vv);
    }
    E[i * BB + j] = (i == j) ? d : d * vv * (1.f / 255.f);
}

// ---------------- final scalar losses ----------------
__global__ void final_kernel(const float* __restrict__ E, const float* __restrict__ l1,
                             const float* __restrict__ l2, float* __restrict__ out) {
    int t = threadIdx.x;
    __shared__ float red[8];
    float r = 0.f, c = 0.f;
    for (int j = 0; j < BB; j++) r += E[t * BB + j];
    for (int i2 = 0; i2 < BB; i2++) c += E[i2 * BB + t];
    float a3 = fmaxf(r + 0.6f, 0.f);
    float a4 = fmaxf(c + 0.6f, 0.f);
    float s3 = blockReduceSum(a3, red);
    float s4 = blockReduceSum(a4, red);
    float s1 = blockReduceSum(l1[t], red);
    float s2 = blockReduceSum(l2[t], red);
    if (t == 0) {
        out[0] = (s1 + s2) * (0.5f / (float)BB);
        out[1] = (s3 + s4) * (0.5f / (float)BB);
    }
}

// ---------------- launch ----------------
extern "C" void kernel_launch(void* const* d_in, const int* in_sizes, int n_in,
                              void* d_out, int out_size) {
    const float* ev   = (const float*)d_in[0];
    const float* ea   = (const float*)d_in[1];
    const int*   masks= (const int*)  d_in[2];
    const float* Wfc1 = (const float*)d_in[3];
    const float* Wfc2 = (const float*)d_in[4];
    const float* Wc1  = (const float*)d_in[5];
    const float* Wc2  = (const float*)d_in[6];
    float* out = (float*)d_out;

    float *hfc, *fa, *faT, *h1, *fv, *ind, *ivn, *ivnT, *invrho, *Sij, *SP, *SN, *E, *l1, *l2, *M;
    __half *Vh, *Vl, *U1h, *U1l, *U2h, *U2l;
    cudaGetSymbolAddress((void**)&hfc,    d_hfc);
    cudaGetSymbolAddress((void**)&fa,     d_fa);
    cudaGetSymbolAddress((void**)&faT,    d_faT);
    cudaGetSymbolAddress((void**)&h1,     d_h1);
    cudaGetSymbolAddress((void**)&fv,     d_fv);
    cudaGetSymbolAddress((void**)&ind,    d_ind);
    cudaGetSymbolAddress((void**)&ivn,    d_ivn);
    cudaGetSymbolAddress((void**)&ivnT,   d_ivnT);
    cudaGetSymbolAddress((void**)&invrho, d_invrho);
    cudaGetSymbolAddress((void**)&Sij,    d_Sij);
    cudaGetSymbolAddress((void**)&SP,     d_SP);
    cudaGetSymbolAddress((void**)&SN,     d_SN);
    cudaGetSymbolAddress((void**)&E,      d_E);
    cudaGetSymbolAddress((void**)&l1,     d_l1);
    cudaGetSymbolAddress((void**)&l2,     d_l2);
    cudaGetSymbolAddress((void**)&M,      d_M);
    cudaGetSymbolAddress((void**)&Vh,     d_Vh);
    cudaGetSymbolAddress((void**)&Vl,     d_Vl);
    cudaGetSymbolAddress((void**)&U1h,    d_U1h);
    cudaGetSymbolAddress((void**)&U1l,    d_U1l);
    cudaGetSymbolAddress((void**)&U2h,    d_U2h);
    cudaGetSymbolAddress((void**)&U2l,    d_U2l);

    // audio branch
    gemm_nt<<<dim3(CD / 16, BB / 16), dim3(16, 16)>>>(ea, Wfc1, hfc, 2048, CD, 1);
    gemm_nt<<<dim3(CD / 16, BB / 16), dim3(16, 16)>>>(hfc, Wfc2, fa, CD, CD, 0);
    transpose_fa<<<512, 256>>>(fa, faT);

    // winograd weight transforms
    wino_wprep<<<(512 * 384 + 255) / 256, 256>>>(Wc1, U1h, U1l, 384);
    wino_wprep<<<(512 * 512 + 255) / 256, 256>>>(Wc2, U2h, U2l, 512);

    // conv1: ev (NCHW) -> h1 [b][p][c], with relu
    wino_inprep_nchw<<<dim3(BB, 384 / 8), 256>>>(ev, Vh, Vl, 384);
    wino_gemm<384><<<dim3(8, 98, 16), 256>>>(Vh, Vl, U1h, U1l, M);
    wino_out<true><<<dim3(BB, NT), 512>>>(M, h1);

    // conv2: h1 -> fv [b][p][c]
    wino_inprep_pc<<<dim3(BB, 7), 256>>>(h1, Vh, Vl);
    wino_gemm<512><<<dim3(8, 98, 16), 256>>>(Vh, Vl, U2h, U2l, M);
    wino_out<false><<<dim3(BB, NT), 512>>>(M, fv);

    // pooling / norms
    indvec_kernel<<<BB, 512>>>(fv, masks, ind);
    invrho_kernel<<<BB, 256>>>(fv, invrho);
    ivn_kernel<<<BB, CD>>>(ind, ivn, ivnT);

    // similarity tensor + exact top-k soft pooling
    sij_gemm<<<dim3(4, 4, BB), dim3(16, 16)>>>(ivn, fv, invrho, Sij);
    topk_radix<<<(BB * BB) / 8, 256>>>(Sij, SP, SN);

    // losses
    loss12_kernel<<<BB, 256>>>(SP, SN, l1, l2);
    dist_kernel<<<BB, 256>>>(ind, ivn, faT, ivnT, E);
    final_kernel<<<1, 256>>>(E, l1, l2, out);
}

// round 12
// speedup vs baseline: 1.6556x; 1.0047x over previous
#include <cuda_runtime.h>
#include <cuda_fp16.h>
#include <math.h>
#include <stdint.h>

// ---------------- problem constants ----------------
#define BB 256
#define HWD 196      // 14*14
#define CD 512
#define NT 49        // 7x7 winograd tiles per image
#define MW (BB*NT)   // 12544 winograd GEMM M
#define TS_INV (1.0f/0.03f)
#define TC_INV (1.0f/0.07f)

// ---------------- scratch (device globals; no runtime allocation) ----------------
__device__ float d_hfc[BB*CD];
__device__ float d_fa[BB*CD];
__device__ float d_faT[CD*BB];
__device__ float d_h1[BB*HWD*CD];     // relu(conv1), layout [b][p][c]
__device__ float d_fv[BB*HWD*CD];     // conv2 out,    layout [b][p][c]
__device__ float d_ind[BB*CD];
__device__ float d_ivn[BB*CD];
__device__ float d_ivnT[CD*BB];
__device__ float d_invrho[BB*HWD];
__device__ float d_Sij[BB*BB*HWD];
__device__ float d_SP[BB*BB];
__device__ float d_SN[BB*BB];
__device__ float d_E[BB*BB];
__device__ float d_l1[BB];
__device__ float d_l2[BB];
// winograd buffers (V/M reused by both convs)
__device__ __half d_Vh[16*MW*CD];     // 205.6 MB
__device__ __half d_Vl[16*MW*CD];
__device__ float  d_M [(size_t)16*MW*CD];  // 411 MB
__device__ __half d_U1h[16*512*384], d_U1l[16*512*384];
__device__ __half d_U2h[16*512*512], d_U2l[16*512*512];

// ---------------- reduction helpers ----------------
__device__ __forceinline__ float warpReduceSum(float v) {
#pragma unroll
    for (int o = 16; o > 0; o >>= 1) v += __shfl_xor_sync(0xffffffffu, v, o);
    return v;
}
__device__ __forceinline__ float warpReduceMax(float v) {
#pragma unroll
    for (int o = 16; o > 0; o >>= 1) v = fmaxf(v, __shfl_xor_sync(0xffffffffu, v, o));
    return v;
}
__device__ __forceinline__ float blockReduceSum(float v, float* red) {
    __syncthreads();
    int lane = threadIdx.x & 31, wid = threadIdx.x >> 5;
    v = warpReduceSum(v);
    if (lane == 0) red[wid] = v;
    __syncthreads();
    int nw = (blockDim.x + 31) >> 5;
    if (wid == 0) {
        float r = (threadIdx.x < nw) ? red[threadIdx.x] : 0.f;
        r = warpReduceSum(r);
        if (lane == 0) red[0] = r;
    }
    __syncthreads();
    return red[0];
}
__device__ __forceinline__ float blockReduceMax(float v, float* red) {
    __syncthreads();
    int lane = threadIdx.x & 31, wid = threadIdx.x >> 5;
    v = warpReduceMax(v);
    if (lane == 0) red[wid] = v;
    __syncthreads();
    int nw = (blockDim.x + 31) >> 5;
    if (wid == 0) {
        float r = (threadIdx.x < nw) ? red[threadIdx.x] : -INFINITY;
        r = warpReduceMax(r);
        if (lane == 0) red[0] = r;
    }
    __syncthreads();
    return red[0];
}

__device__ __forceinline__ float sigmoidf_stable(float x) {
    if (x >= 0.f) { float e = expf(-x); return 1.f / (1.f + e); }
    float e = expf(x); return e / (1.f + e);
}

// ---------------- fp16 mma m16n8k16 ----------------
__device__ __forceinline__ void mma_f16(float c[4], const uint32_t a[4], uint32_t b0, uint32_t b1) {
    asm volatile(
        "mma.sync.aligned.m16n8k16.row.col.f32.f16.f16.f32 "
        "{%0,%1,%2,%3}, {%4,%5,%6,%7}, {%8,%9}, {%0,%1,%2,%3};"
        : "+f"(c[0]), "+f"(c[1]), "+f"(c[2]), "+f"(c[3])
        : "r"(a[0]), "r"(a[1]), "r"(a[2]), "r"(a[3]), "r"(b0), "r"(b1));
}

// ---------------- order-preserving float<->key ----------------
__device__ __forceinline__ uint32_t f2key(float f) {
    uint32_t u = __float_as_uint(f);
    return (u & 0x80000000u) ? ~u : (u | 0x80000000u);
}
__device__ __forceinline__ float key2f(uint32_t k) {
    return __uint_as_float((k & 0x80000000u) ? (k ^ 0x80000000u) : ~k);
}

// ---------------- winograd split-store helper ----------------
__device__ __forceinline__ void split_store(float v, __half* ph, __half* pl) {
    __half h = __float2half_rn(v);
    *ph = h;
    *pl = __float2half_rn(v - __half2float(h));
}

// ---------------- weight transform: U = G g G^T, per (oc, ic) ----------------
// w layout [oc][ic][3][3]; U layout [k16][oc 512][ic IC]
__global__ void wino_wprep(const float* __restrict__ w, __half* __restrict__ Uh,
                           __half* __restrict__ Ul, int IC) {
    int idx = blockIdx.x * 256 + threadIdx.x;
    if (idx >= 512 * IC) return;
    int oc = idx / IC, ic = idx % IC;
    float g[3][3];
#pragma unroll
    for (int r = 0; r < 3; r++)
#pragma unroll
        for (int c = 0; c < 3; c++) g[r][c] = w[((size_t)idx) * 9 + r * 3 + c];
    float t[4][3];
#pragma unroll
    for (int c = 0; c < 3; c++) {
        t[0][c] = g[0][c];
        t[1][c] = 0.5f * (g[0][c] + g[1][c] + g[2][c]);
        t[2][c] = 0.5f * (g[0][c] - g[1][c] + g[2][c]);
        t[3][c] = g[2][c];
    }
#pragma unroll
    for (int r = 0; r < 4; r++) {
        float u0 = t[r][0];
        float u1 = 0.5f * (t[r][0] + t[r][1] + t[r][2]);
        float u2 = 0.5f * (t[r][0] - t[r][1] + t[r][2]);
        float u3 = t[r][2];
        float uu[4] = {u0, u1, u2, u3};
#pragma unroll
        for (int c = 0; c < 4; c++) {
            size_t off = ((size_t)(r * 4 + c) * 512 + oc) * IC + ic;
            split_store(uu[c], Uh + off, Ul + off);
        }
    }
}

// ---------------- input transform V = B^T d B ----------------
__device__ __forceinline__ void wino_Vcalc(const float d[4][4], float V[16]) {
    float t[4][4];
#pragma unroll
    for (int c = 0; c < 4; c++) {
        t[0][c] = d[0][c] - d[2][c];
        t[1][c] = d[1][c] + d[2][c];
        t[2][c] = d[2][c] - d[1][c];
        t[3][c] = d[1][c] - d[3][c];
    }
#pragma unroll
    for (int r = 0; r < 4; r++) {
        V[r * 4 + 0] = t[r][0] - t[r][2];
        V[r * 4 + 1] = t[r][1] + t[r][2];
        V[r * 4 + 2] = t[r][2] - t[r][1];
        V[r * 4 + 3] = t[r][1] - t[r][3];
    }
}

// input in NCHW (ev): grid (256 b, IC/8), block 256; smem 8 planes
__global__ void wino_inprep_nchw(const float* __restrict__ in, __half* __restrict__ Vh,
                                 __half* __restrict__ Vl, int IC) {
    __shared__ float plane[8][HWD];
    int b = blockIdx.x;
    int ic0 = blockIdx.y * 8;
    for (int e = threadIdx.x; e < 8 * HWD; e += 256) {
        int ic = e / HWD, p = e % HWD;
        plane[ic][p] = in[((size_t)b * IC + ic0 + ic) * HWD + p];
    }
    __syncthreads();
    for (int e = threadIdx.x; e < 8 * NT; e += 256) {
        int ic = e & 7, t = e >> 3;
        int ty = t / 7, tx = t % 7;
        float d[4][4];
#pragma unroll
        for (int r = 0; r < 4; r++) {
            int iy = 2 * ty - 1 + r;
#pragma unroll
            for (int c = 0; c < 4; c++) {
                int ix = 2 * tx - 1 + c;
                d[r][c] = (iy >= 0 && iy < 14 && ix >= 0 && ix < 14) ? plane[ic][iy * 14 + ix] : 0.f;
            }
        }
        float V[16];
        wino_Vcalc(d, V);
        int m = b * NT + t;
#pragma unroll
        for (int k = 0; k < 16; k++) {
            size_t off = ((size_t)k * MW + m) * IC + ic0 + ic;
            split_store(V[k], Vh + off, Vl + off);
        }
    }
}

// input in [b][p][c] (h1): grid (256 b, 7 tchunk), block 256
__global__ void wino_inprep_pc(const float* __restrict__ in, __half* __restrict__ Vh,
                               __half* __restrict__ Vl) {
    int b = blockIdx.x;
    const float* ib = in + (size_t)b * HWD * CD;
    for (int e = threadIdx.x; e < 7 * CD; e += 256) {
        int ic = e & (CD - 1), tl = e >> 9;
        int t = blockIdx.y * 7 + tl;
        int ty = t / 7, tx = t % 7;
        float d[4][4];
#pragma unroll
        for (int r = 0; r < 4; r++) {
            int iy = 2 * ty - 1 + r;
#pragma unroll
            for (int c = 0; c < 4; c++) {
                int ix = 2 * tx - 1 + c;
                d[r][c] = (iy >= 0 && iy < 14 && ix >= 0 && ix < 14)
                          ? ib[(size_t)(iy * 14 + ix) * CD + ic] : 0.f;
            }
        }
        float V[16];
        wino_Vcalc(d, V);
        int m = b * NT + t;
#pragma unroll
        for (int k = 0; k < 16; k++) {
            size_t off = ((size_t)k * MW + m) * CD + ic;
            split_store(V[k], Vh + off, Vl + off);
        }
    }
}

// ---------------- winograd GEMM: M[k][m][oc] = sum_ic V[k][m][ic]*U[k][oc][ic] ----------------
// grid (8 octile, 98 mtile, 16 k), block 256 (8 warps = 4 ocgroups x 2 mhalves)
// fp16 hi/lo 3-MMA split; fragment conventions identical to R4's passing conv kernel.
template<int IC>
__global__ void __launch_bounds__(256) wino_gemm(const __half* __restrict__ Vh,
                                                 const __half* __restrict__ Vl,
                                                 const __half* __restrict__ Uh,
                                                 const __half* __restrict__ Ul,
                                                 float* __restrict__ Mout) {
    __shared__ uint32_t Ush[16][72], Usl[16][72];   // [icpair][oc64]
    __shared__ uint32_t Vsh[16][136], Vsl[16][136]; // [icpair][m128]

    const int oc0 = blockIdx.x * 64;
    const int m0 = blockIdx.y * 128;
    const int k = blockIdx.z;
    const int tid = threadIdx.x;
    const int warp = tid >> 5, lane = tid & 31;
    const int gid = lane >> 2, tig = lane & 3;
    const int ocw = (warp >> 1) * 16;
    const int mhalf = (warp & 1) * 64;

    float C[8][4];
#pragma unroll
    for (int mt = 0; mt < 8; mt++)
#pragma unroll
        for (int r = 0; r < 4; r++) C[mt][r] = 0.f;

    const __half* Ukh = Uh + (size_t)k * 512 * IC;
    const __half* Ukl = Ul + (size_t)k * 512 * IC;
    const __half* Vkh = Vh + (size_t)k * MW * IC;
    const __half* Vkl = Vl + (size_t)k * MW * IC;

    for (int ic0 = 0; ic0 < IC; ic0 += 32) {
        __syncthreads();
        for (int e = tid; e < 1024; e += 256) {
            int pr = e & 15, o = e >> 4;
            size_t off = (size_t)(oc0 + o) * IC + ic0 + 2 * pr;
            Ush[pr][o] = *(const uint32_t*)(Ukh + off);
            Usl[pr][o] = *(const uint32_t*)(Ukl + off);
        }
        for (int e = tid; e < 2048; e += 256) {
            int pr = e & 15, m = e >> 4;
            size_t off = (size_t)(m0 + m) * IC + ic0 + 2 * pr;
            Vsh[pr][m] = *(const uint32_t*)(Vkh + off);
            Vsl[pr][m] = *(const uint32_t*)(Vkl + off);
        }
        __syncthreads();
#pragma unroll
        for (int ks = 0; ks < 2; ks++) {
            const int kp = ks * 8;
            uint32_t ahi[4], alo[4];
            ahi[0] = Ush[kp + tig][ocw + gid];
            ahi[1] = Ush[kp + tig][ocw + gid + 8];
            ahi[2] = Ush[kp + 4 + tig][ocw + gid];
            ahi[3] = Ush[kp + 4 + tig][ocw + gid + 8];
            alo[0] = Usl[kp + tig][ocw + gid];
            alo[1] = Usl[kp + tig][ocw + gid + 8];
            alo[2] = Usl[kp + 4 + tig][ocw + gid];
            alo[3] = Usl[kp + 4 + tig][ocw + gid + 8];
#pragma unroll
            for (int mt = 0; mt < 8; mt++) {
                const int mc = mhalf + mt * 8 + gid;
                uint32_t b0h = Vsh[kp + tig][mc];
                uint32_t b1h = Vsh[kp + 4 + tig][mc];
                uint32_t b0l = Vsl[kp + tig][mc];
                uint32_t b1l = Vsl[kp + 4 + tig][mc];
                mma_f16(C[mt], ahi, b0h, b1h);
                mma_f16(C[mt], alo, b0h, b1h);
                mma_f16(C[mt], ahi, b0l, b1l);
            }
        }
    }

    // store: D row = oc (gid), col = m (tig*2, tig*2+1); rows +8 in c2/c3
    float* Mk = Mout + (size_t)k * MW * 512;
#pragma unroll
    for (int mt = 0; mt < 8; mt++) {
        int m = m0 + mhalf + mt * 8 + tig * 2;
        int oc = oc0 + ocw + gid;
        float* mp = Mk + (size_t)m * 512 + oc;
        mp[0] = C[mt][0];
        mp[512] = C[mt][1];
        mp[8] = C[mt][2];
        mp[512 + 8] = C[mt][3];
    }
}

// ---------------- output inverse transform: Y = A^T M A -> out[b][p][c] ----------------
template<bool RELU>
__global__ void wino_out(const float* __restrict__ Min, float* __restrict__ out) {
    int b = blockIdx.x, t = blockIdx.y;
    int oc = threadIdx.x;   // 512
    int m = b * NT + t;
    float M[16];
#pragma unroll
    for (int k = 0; k < 16; k++) M[k] = Min[((size_t)k * MW + m) * 512 + oc];
    float tr[2][4];
#pragma unroll
    for (int c = 0; c < 4; c++) {
        tr[0][c] = M[0 * 4 + c] + M[1 * 4 + c] + M[2 * 4 + c];
        tr[1][c] = M[1 * 4 + c] - M[2 * 4 + c] - M[3 * 4 + c];
    }
    int ty = t / 7, tx = t % 7;
    float* ob = out + (size_t)b * HWD * CD + oc;
#pragma unroll
    for (int r = 0; r < 2; r++) {
        float y0 = tr[r][0] + tr[r][1] + tr[r][2];
        float y1 = tr[r][1] - tr[r][2] - tr[r][3];
        if (RELU) { y0 = fmaxf(y0, 0.f); y1 = fmaxf(y1, 0.f); }
        int p = (2 * ty + r) * 14 + 2 * tx;
        ob[(size_t)p * CD] = y0;
        ob[(size_t)(p + 1) * CD] = y1;
    }
}

// ---------------- GEMM: C[m,n] = sum_k A[m,k] * W[n,k], optional relu ----------------
__global__ void gemm_nt(const float* __restrict__ A, const float* __restrict__ W,
                        float* __restrict__ C, int K, int N, int relu) {
    __shared__ float As[16][17], Ws[16][17];
    int tx = threadIdx.x, ty = threadIdx.y;
    int m = blockIdx.y * 16 + ty;
    int n0 = blockIdx.x * 16;
    float acc = 0.f;
    for (int k0 = 0; k0 < K; k0 += 16) {
        As[ty][tx] = A[m * K + k0 + tx];
        Ws[ty][tx] = W[(n0 + ty) * K + k0 + tx];
        __syncthreads();
#pragma unroll
        for (int kk = 0; kk < 16; kk++) acc = fmaf(As[ty][kk], Ws[tx][kk], acc);
        __syncthreads();
    }
    C[m * N + n0 + tx] = relu ? fmaxf(acc, 0.f) : acc;
}

// ---------------- masked mean pooling (fv [b][p][c]) -> ind_vec ----------------
__global__ void indvec_kernel(const float* __restrict__ fv, const int* __restrict__ masks,
                              float* __restrict__ ind) {
    int b = blockIdx.x;
    int c = threadIdx.x;   // 512
    __shared__ float m_s[HWD];
    __shared__ float red[16];
    float mv = 0.f;
    if (c < HWD) { mv = (float)masks[b * HWD + c]; m_s[c] = mv; }
    float tot = blockReduceSum(mv, red);
    float inv_m = 1.f / tot;
    const float* fb = fv + (size_t)b * HWD * CD + c;
    float s = 0.f;
    for (int p = 0; p < HWD; p++) s = fmaf(fb[(size_t)p * CD], m_s[p], s);
    ind[b * CD + c] = s * inv_m;
}

// ---------------- per (b,p) inverse channel L2 norm (fv [b][p][c]) ----------------
__global__ void invrho_kernel(const float* __restrict__ fv, float* __restrict__ invrho) {
    int b = blockIdx.x;
    int lane = threadIdx.x & 31, w = threadIdx.x >> 5;  // 8 warps
    for (int p = w; p < HWD; p += 8) {
        const float* row = fv + ((size_t)b * HWD + p) * CD;
        float s = 0.f;
        for (int c = lane; c < CD; c += 32) { float v = row[c]; s = fmaf(v, v, s); }
        s = warpReduceSum(s);
        if (lane == 0) invrho[b * HWD + p] = 1.f / fmaxf(sqrtf(s), 1e-12f);
    }
}

// ---------------- normalize ind_vec -> ivn (+ transposed copy) ----------------
__global__ void ivn_kernel(const float* __restrict__ ind, float* __restrict__ ivn,
                           float* __restrict__ ivnT) {
    int b = blockIdx.x, c = threadIdx.x;
    __shared__ float red[16];
    float v = ind[b * CD + c];
    float ss = blockReduceSum(v * v, red);
    float o = v / fmaxf(sqrtf(ss), 1e-12f);
    ivn[b * CD + c] = o;
    ivnT[c * BB + b] = o;
}

// ---------------- transpose fa ----------------
__global__ void transpose_fa(const float* __restrict__ fa, float* __restrict__ faT) {
    int idx = blockIdx.x * 256 + threadIdx.x;
    int b = idx >> 9, c = idx & 511;
    faT[c * BB + b] = fa[idx];
}

// ---------------- Sij[i,j,p] = <ivn[j], fv[i,p,:]> * invrho[i,p] ----------------
__global__ void sij_gemm(const float* __restrict__ ivn, const float* __restrict__ fv,
                         const float* __restrict__ invrho, float* __restrict__ Sij) {
    int i = blockIdx.z;
    int p0 = blockIdx.x * 64;
    int j0 = blockIdx.y * 64;
    __shared__ float As[64][17];
    __shared__ float Bs[16][65];
    int tid = threadIdx.y * 16 + threadIdx.x;
    float acc[4][4] = {};
    const float* fvi = fv + (size_t)i * HWD * CD;
    for (int k0 = 0; k0 < CD; k0 += 16) {
#pragma unroll
        for (int r = 0; r < 4; r++) {
            int e = tid + r * 256;
            int row = e >> 4, col = e & 15;
            As[row][col] = ivn[(j0 + row) * CD + k0 + col];
        }
#pragma unroll
        for (int r = 0; r < 4; r++) {
            int e = tid + r * 256;
            int cs = e & 15, p = e >> 4;     // fv [p][c]: c fastest -> coalesced
            int pg = p0 + p;
            Bs[cs][p] = (pg < HWD) ? fvi[(size_t)pg * CD + k0 + cs] : 0.f;
        }
        __syncthreads();
#pragma unroll
        for (int kk = 0; kk < 16; kk++) {
            float a[4], bb[4];
#pragma unroll
            for (int r = 0; r < 4; r++) a[r] = As[threadIdx.y * 4 + r][kk];
#pragma unroll
            for (int c = 0; c < 4; c++) bb[c] = Bs[kk][threadIdx.x * 4 + c];
#pragma unroll
            for (int r = 0; r < 4; r++)
#pragma unroll
                for (int c = 0; c < 4; c++)
                    acc[r][c] = fmaf(a[r], bb[c], acc[r][c]);
        }
        __syncthreads();
    }
#pragma unroll
    for (int r = 0; r < 4; r++) {
        int j = j0 + threadIdx.y * 4 + r;
#pragma unroll
        for (int c = 0; c < 4; c++) {
            int p = p0 + threadIdx.x * 4 + c;
            if (p < HWD)
                Sij[((size_t)(i * BB + j)) * HWD + p] = acc[r][c] * invrho[i * HWD + p];
        }
    }
}

// ---------------- warp-per-row dual radix-select + soft-mask pooling ----------------
__global__ void topk_radix(const float* __restrict__ Sij, float* __restrict__ SP,
                           float* __restrict__ SN) {
    int row = (blockIdx.x * blockDim.x + threadIdx.x) >> 5;
    int lane = threadIdx.x & 31;
    const float* rp = Sij + (size_t)row * HWD;

    float v[7];
    uint32_t key[7];
#pragma unroll
    for (int e = 0; e < 7; e++) {
        int p = e * 32 + lane;
        bool valid = (p < HWD);
        v[e] = valid ? rp[p] : 0.f;
        key[e] = valid ? f2key(v[e]) : 0u;
    }

    uint32_t p1 = 0, p2 = 0;
#pragma unroll
    for (int b = 31; b >= 0; b--) {
        uint32_t c1 = (p1 >> b) | 1u;
        uint32_t c2 = (p2 >> b) | 1u;
        int n = 0;
#pragma unroll
        for (int e = 0; e < 7; e++) {
            uint32_t t = key[e] >> b;
            n += (t >= c1) ? 1 : 0;
            n += (t >= c2) ? 0x10000 : 0;
        }
        n = __reduce_add_sync(0xffffffffu, n);
        if ((n & 0xffff) >= 19) p1 |= (1u << b);
        if ((n >> 16) >= 99)    p2 |= (1u << b);
    }
    float pthr = key2f(p1);
    float nthr = key2f(p2);

    float svp = 0.f, sp = 0.f, svn = 0.f, sn = 0.f;
#pragma unroll
    for (int e = 0; e < 7; e++) {
        int p = e * 32 + lane;
        if (p < HWD) {
            float mp = sigmoidf_stable((v[e] - pthr) * TS_INV);
            float mn = 1.f - sigmoidf_stable((v[e] - nthr) * TS_INV);
            svp += v[e] * mp; sp += mp;
            svn += v[e] * mn; sn += mn;
        }
    }
    svp = warpReduceSum(svp); sp = warpReduceSum(sp);
    svn = warpReduceSum(svn); sn = warpReduceSum(sn);
    if (lane == 0) {
        SP[row] = svp / sp;
        SN[row] = svn / sn;
    }
}

// ---------------- contrastive losses ----------------
__global__ void loss12_kernel(const float* __restrict__ SP, const float* __restrict__ SN,
                              float* __restrict__ l1, float* __restrict__ l2) {
    int i = blockIdx.x, j = threadIdx.x;
    __shared__ float red[8];
    float a1 = SP[i * BB + j] * TC_INV, a2 = SN[i * BB + j] * TC_INV;
    float b1 = SP[j * BB + i] * TC_INV, b2 = SN[j * BB + i] * TC_INV;
    float m1 = blockReduceMax(fmaxf(a1, a2), red);
    float s1 = blockReduceSum(expf(a1 - m1) + expf(a2 - m1), red);
    float m2 = blockReduceMax(fmaxf(b1, b2), red);
    float s2 = blockReduceSum(expf(b1 - m2) + expf(b2 - m2), red);
    if (j == 0) {
        float diag = SP[i * BB + i] * TC_INV;
        l1[i] = logf(s1) + m1 - diag;
        l2[i] = logf(s2) + m2 - diag;
    }
}

// ---------------- weighted pairwise-distance matrix E ----------------
__global__ void dist_kernel(const float* __restrict__ ind, const float* __restrict__ ivn,
                            const float* __restrict__ faT, const float* __restrict__ ivnT,
                            float* __restrict__ E) {
    int i = blockIdx.x, j = threadIdx.x;
    __shared__ float ind_s[CD], ivn_s[CD];
    for (int c = j; c < CD; c += 256) { ind_s[c] = ind[i * CD + c]; ivn_s[c] = ivn[i * CD + c]; }
    __syncthreads();
    float d = 0.f, vv = 0.f;
    for (int c = 0; c < CD; c++) {
        float t = ind_s[c] - faT[c * BB + j] + 1e-6f;
        d = fmaf(t, t, d);
        vv = fmaf(ivn_s[c], ivnT[c * BB + j], vv);
    }
    E[i * BB + j] = (i == j) ? d : d * vv * (1.f / 255.f);
}

// ---------------- final scalar losses ----------------
__global__ void final_kernel(const float* __restrict__ E, const float* __restrict__ l1,
                             const float* __restrict__ l2, float* __restrict__ out) {
    int t = threadIdx.x;
    __shared__ float red[8];
    float r = 0.f, c = 0.f;
    for (int j = 0; j < BB; j++) r += E[t * BB + j];
    for (int i2 = 0; i2 < BB; i2++) c += E[i2 * BB + t];
    float a3 = fmaxf(r + 0.6f, 0.f);
    float a4 = fmaxf(c + 0.6f, 0.f);
    float s3 = blockReduceSum(a3, red);
    float s4 = blockReduceSum(a4, red);
    float s1 = blockReduceSum(l1[t], red);
    float s2 = blockReduceSum(l2[t], red);
    if (t == 0) {
        out[0] = (s1 + s2) * (0.5f / (float)BB);
        out[1] = (s3 + s4) * (0.5f / (float)BB);
    }
}

// ---------------- launch ----------------
extern "C" void kernel_launch(void* const* d_in, const int* in_sizes, int n_in,
                              void* d_out, int out_size) {
    const float* ev   = (const float*)d_in[0];
    const float* ea   = (const float*)d_in[1];
    const int*   masks= (const int*)  d_in[2];
    const float* Wfc1 = (const float*)d_in[3];
    const float* Wfc2 = (const float*)d_in[4];
    const float* Wc1  = (const float*)d_in[5];
    const float* Wc2  = (const float*)d_in[6];
    float* out = (float*)d_out;

    float *hfc, *fa, *faT, *h1, *fv, *ind, *ivn, *ivnT, *invrho, *Sij, *SP, *SN, *E, *l1, *l2, *M;
    __half *Vh, *Vl, *U1h, *U1l, *U2h, *U2l;
    cudaGetSymbolAddress((void**)&hfc,    d_hfc);
    cudaGetSymbolAddress((void**)&fa,     d_fa);
    cudaGetSymbolAddress((void**)&faT,    d_faT);
    cudaGetSymbolAddress((void**)&h1,     d_h1);
    cudaGetSymbolAddress((void**)&fv,     d_fv);
    cudaGetSymbolAddress((void**)&ind,    d_ind);
    cudaGetSymbolAddress((void**)&ivn,    d_ivn);
    cudaGetSymbolAddress((void**)&ivnT,   d_ivnT);
    cudaGetSymbolAddress((void**)&invrho, d_invrho);
    cudaGetSymbolAddress((void**)&Sij,    d_Sij);
    cudaGetSymbolAddress((void**)&SP,     d_SP);
    cudaGetSymbolAddress((void**)&SN,     d_SN);
    cudaGetSymbolAddress((void**)&E,      d_E);
    cudaGetSymbolAddress((void**)&l1,     d_l1);
    cudaGetSymbolAddress((void**)&l2,     d_l2);
    cudaGetSymbolAddress((void**)&M,      d_M);
    cudaGetSymbolAddress((void**)&Vh,     d_Vh);
    cudaGetSymbolAddress((void**)&Vl,     d_Vl);
    cudaGetSymbolAddress((void**)&U1h,    d_U1h);
    cudaGetSymbolAddress((void**)&U1l,    d_U1l);
    cudaGetSymbolAddress((void**)&U2h,    d_U2h);
    cudaGetSymbolAddress((void**)&U2l,    d_U2l);

    // audio branch
    gemm_nt<<<dim3(CD / 16, BB / 16), dim3(16, 16)>>>(ea, Wfc1, hfc, 2048, CD, 1);
    gemm_nt<<<dim3(CD / 16, BB / 16), dim3(16, 16)>>>(hfc, Wfc2, fa, CD, CD, 0);
    transpose_fa<<<512, 256>>>(fa, faT);

    // winograd weight transforms
    wino_wprep<<<(512 * 384 + 255) / 256, 256>>>(Wc1, U1h, U1l, 384);
    wino_wprep<<<(512 * 512 + 255) / 256, 256>>>(Wc2, U2h, U2l, 512);

    // conv1: ev (NCHW) -> h1 [b][p][c], with relu
    wino_inprep_nchw<<<dim3(BB, 384 / 8), 256>>>(ev, Vh, Vl, 384);
    wino_gemm<384><<<dim3(8, 98, 16), 256>>>(Vh, Vl, U1h, U1l, M);
    wino_out<true><<<dim3(BB, NT), 512>>>(M, h1);

    // conv2: h1 -> fv [b][p][c]
    wino_inprep_pc<<<dim3(BB, 7), 256>>>(h1, Vh, Vl);
    wino_gemm<512><<<dim3(8, 98, 16), 256>>>(Vh, Vl, U2h, U2l, M);
    wino_out<false><<<dim3(BB, NT), 512>>>(M, fv);

    // pooling / norms
    indvec_kernel<<<BB, 512>>>(fv, masks, ind);
    invrho_kernel<<<BB, 256>>>(fv, invrho);
    ivn_kernel<<<BB, CD>>>(ind, ivn, ivnT);

    // similarity tensor + exact top-k soft pooling
    sij_gemm<<<dim3(4, 4, BB), dim3(16, 16)>>>(ivn, fv, invrho, Sij);
    topk_radix<<<(BB * BB) / 8, 256>>>(Sij, SP, SN);

    // losses
    loss12_kernel<<<BB, 256>>>(SP, SN, l1, l2);
    dist_kernel<<<BB, 256>>>(ind, ivn, faT, ivnT, E);
    final_kernel<<<1, 256>>>(E, l1, l2, out);
}

// round 16
// speedup vs baseline: 2.1057x; 1.2719x over previous
#include <cuda_runtime.h>
#include <cuda_fp16.h>
#include <math.h>
#include <stdint.h>

// ---------------- problem constants ----------------
#define BB 256
#define HWD 196      // 14*14
#define CD 512
#define NT4 16       // 4x4 winograd F(4x4,3x3) tiles per image
#define MW4 (BB*NT4) // 4096 winograd GEMM M
#define TS_INV (1.0f/0.03f)
#define TC_INV (1.0f/0.07f)

// ---------------- scratch (device globals; no runtime allocation) ----------------
__device__ float d_hfc[BB*CD];
__device__ float d_fa[BB*CD];
__device__ float d_faT[CD*BB];
__device__ float d_h1[BB*HWD*CD];     // relu(conv1), layout [b][p][c]
__device__ float d_fv[BB*HWD*CD];     // conv2 out,    layout [b][p][c]
__device__ float d_ind[BB*CD];
__device__ float d_ivn[BB*CD];
__device__ float d_ivnT[CD*BB];
__device__ float d_invrho[BB*HWD];
__device__ float d_Sij[BB*BB*HWD];
__device__ float d_SP[BB*BB];
__device__ float d_SN[BB*BB];
__device__ float d_E[BB*BB];
__device__ float d_l1[BB];
__device__ float d_l2[BB];
// winograd buffers (V/M reused by both convs); 36 k-matrices
__device__ __half d_Vh[36*MW4*CD];    // 151 MB
__device__ __half d_Vl[36*MW4*CD];
__device__ float  d_M [36*MW4*CD];    // 302 MB
__device__ __half d_U1h[36*512*384], d_U1l[36*512*384];
__device__ __half d_U2h[36*512*512], d_U2l[36*512*512];

// ---------------- reduction helpers ----------------
__device__ __forceinline__ float warpReduceSum(float v) {
#pragma unroll
    for (int o = 16; o > 0; o >>= 1) v += __shfl_xor_sync(0xffffffffu, v, o);
    return v;
}
__device__ __forceinline__ float warpReduceMax(float v) {
#pragma unroll
    for (int o = 16; o > 0; o >>= 1) v = fmaxf(v, __shfl_xor_sync(0xffffffffu, v, o));
    return v;
}
__device__ __forceinline__ float blockReduceSum(float v, float* red) {
    __syncthreads();
    int lane = threadIdx.x & 31, wid = threadIdx.x >> 5;
    v = warpReduceSum(v);
    if (lane == 0) red[wid] = v;
    __syncthreads();
    int nw = (blockDim.x + 31) >> 5;
    if (wid == 0) {
        float r = (threadIdx.x < nw) ? red[threadIdx.x] : 0.f;
        r = warpReduceSum(r);
        if (lane == 0) red[0] = r;
    }
    __syncthreads();
    return red[0];
}
__device__ __forceinline__ float blockReduceMax(float v, float* red) {
    __syncthreads();
    int lane = threadIdx.x & 31, wid = threadIdx.x >> 5;
    v = warpReduceMax(v);
    if (lane == 0) red[wid] = v;
    __syncthreads();
    int nw = (blockDim.x + 31) >> 5;
    if (wid == 0) {
        float r = (threadIdx.x < nw) ? red[threadIdx.x] : -INFINITY;
        r = warpReduceMax(r);
        if (lane == 0) red[0] = r;
    }
    __syncthreads();
    return red[0];
}

__device__ __forceinline__ float sigmoidf_stable(float x) {
    if (x >= 0.f) { float e = expf(-x); return 1.f / (1.f + e); }
    float e = expf(x); return e / (1.f + e);
}

// ---------------- fp16 mma m16n8k16 ----------------
__device__ __forceinline__ void mma_f16(float c[4], const uint32_t a[4], uint32_t b0, uint32_t b1) {
    asm volatile(
        "mma.sync.aligned.m16n8k16.row.col.f32.f16.f16.f32 "
        "{%0,%1,%2,%3}, {%4,%5,%6,%7}, {%8,%9}, {%0,%1,%2,%3};"
        : "+f"(c[0]), "+f"(c[1]), "+f"(c[2]), "+f"(c[3])
        : "r"(a[0]), "r"(a[1]), "r"(a[2]), "r"(a[3]), "r"(b0), "r"(b1));
}

// ---------------- order-preserving float<->key ----------------
__device__ __forceinline__ uint32_t f2key(float f) {
    uint32_t u = __float_as_uint(f);
    return (u & 0x80000000u) ? ~u : (u | 0x80000000u);
}
__device__ __forceinline__ float key2f(uint32_t k) {
    return __uint_as_float((k & 0x80000000u) ? (k ^ 0x80000000u) : ~k);
}

// ---------------- winograd split-store helper ----------------
__device__ __forceinline__ void split_store(float v, __half* ph, __half* pl) {
    __half h = __float2half_rn(v);
    *ph = h;
    *pl = __float2half_rn(v - __half2float(h));
}

// ---------------- F(4x4,3x3) transform helpers (canonical Lavin matrices) ----------------
// B^T row transform of a 6-vector
__device__ __forceinline__ void bt6(const float a[6], float w[6]) {
    w[0] =  4.f * a[0] - 5.f * a[2] + a[4];
    w[1] = -4.f * a[1] - 4.f * a[2] + a[3] + a[4];
    w[2] =  4.f * a[1] - 4.f * a[2] - a[3] + a[4];
    w[3] = -2.f * a[1] - a[2] + 2.f * a[3] + a[4];
    w[4] =  2.f * a[1] - a[2] - 2.f * a[3] + a[4];
    w[5] =  4.f * a[1] - 5.f * a[3] + a[5];
}
// G transform of a 3-vector
__device__ __forceinline__ void g6(float a0, float a1, float a2, float w[6]) {
    w[0] = 0.25f * a0;
    w[1] = (-a0 - a1 - a2) * (1.f / 6.f);
    w[2] = (-a0 + a1 - a2) * (1.f / 6.f);
    w[3] = a0 * (1.f / 24.f) + a1 * (1.f / 12.f) + a2 * (1.f / 6.f);
    w[4] = a0 * (1.f / 24.f) - a1 * (1.f / 12.f) + a2 * (1.f / 6.f);
    w[5] = a2;
}
// A^T transform of a 6-vector -> 4
__device__ __forceinline__ void at6(const float a[6], float y[4]) {
    y[0] = a[0] + a[1] + a[2] + a[3] + a[4];
    y[1] = a[1] - a[2] + 2.f * (a[3] - a[4]);
    y[2] = a[1] + a[2] + 4.f * (a[3] + a[4]);
    y[3] = a[1] - a[2] + 8.f * (a[3] - a[4]) + a[5];
}

// ---------------- weight transform: U = G g G^T -> [k36][oc][ic] ----------------
__global__ void wino4_wprep(const float* __restrict__ w, __half* __restrict__ Uh,
                            __half* __restrict__ Ul, int IC) {
    int idx = blockIdx.x * 256 + threadIdx.x;
    if (idx >= 512 * IC) return;
    int oc = idx / IC, ic = idx % IC;
    float g[3][3];
#pragma unroll
    for (int r = 0; r < 3; r++)
#pragma unroll
        for (int c = 0; c < 3; c++) g[r][c] = w[((size_t)idx) * 9 + r * 3 + c];
    float t[6][3];
#pragma unroll
    for (int c = 0; c < 3; c++) {
        float col[6];
        g6(g[0][c], g[1][c], g[2][c], col);
#pragma unroll
        for (int r = 0; r < 6; r++) t[r][c] = col[r];
    }
#pragma unroll
    for (int r = 0; r < 6; r++) {
        float row[6];
        g6(t[r][0], t[r][1], t[r][2], row);
#pragma unroll
        for (int c = 0; c < 6; c++) {
            size_t off = ((size_t)(r * 6 + c) * 512 + oc) * IC + ic;
            split_store(row[c], Uh + off, Ul + off);
        }
    }
}

// ---------------- input transform V = B^T d B ----------------
__device__ __forceinline__ void wino4_V(const float d[6][6], float V[36]) {
    float t[6][6];
#pragma unroll
    for (int c = 0; c < 6; c++) {
        float a[6], w[6];
#pragma unroll
        for (int r = 0; r < 6; r++) a[r] = d[r][c];
        bt6(a, w);
#pragma unroll
        for (int r = 0; r < 6; r++) t[r][c] = w[r];
    }
#pragma unroll
    for (int r = 0; r < 6; r++) {
        float w[6];
        bt6(t[r], w);
#pragma unroll
        for (int c = 0; c < 6; c++) V[r * 6 + c] = w[c];
    }
}

// conv1 input: NCHW. grid (BB, IC/16), block 256 (16 ic x 16 tiles)
__global__ void wino4_in_nchw(const float* __restrict__ in, __half* __restrict__ Vh,
                              __half* __restrict__ Vl, int IC) {
    __shared__ float plane[16][HWD];
    int b = blockIdx.x;
    int ic0 = blockIdx.y * 16;
    for (int e = threadIdx.x; e < 16 * HWD; e += 256) {
        int ic = e / HWD, p = e % HWD;
        plane[ic][p] = in[((size_t)b * IC + ic0 + ic) * HWD + p];
    }
    __syncthreads();
    int ic = threadIdx.x & 15;
    int t = threadIdx.x >> 4;
    int ty = t >> 2, tx = t & 3;
    float d[6][6];
#pragma unroll
    for (int r = 0; r < 6; r++) {
        int iy = 4 * ty - 1 + r;
#pragma unroll
        for (int c = 0; c < 6; c++) {
            int ix = 4 * tx - 1 + c;
            d[r][c] = (iy >= 0 && iy < 14 && ix >= 0 && ix < 14) ? plane[ic][iy * 14 + ix] : 0.f;
        }
    }
    float V[36];
    wino4_V(d, V);
    int m = b * NT4 + t;
#pragma unroll
    for (int k = 0; k < 36; k++) {
        size_t off = ((size_t)k * MW4 + m) * IC + ic0 + ic;
        split_store(V[k], Vh + off, Vl + off);
    }
}

// conv2 input: [b][p][c]. grid (BB, 16 tiles), block 512 (ic)
__global__ void wino4_in_pc(const float* __restrict__ in, __half* __restrict__ Vh,
                            __half* __restrict__ Vl) {
    int b = blockIdx.x;
    int t = blockIdx.y;
    int ic = threadIdx.x;
    int ty = t >> 2, tx = t & 3;
    const float* ib = in + (size_t)b * HWD * CD + ic;
    float d[6][6];
#pragma unroll
    for (int r = 0; r < 6; r++) {
        int iy = 4 * ty - 1 + r;
#pragma unroll
        for (int c = 0; c < 6; c++) {
            int ix = 4 * tx - 1 + c;
            d[r][c] = (iy >= 0 && iy < 14 && ix >= 0 && ix < 14)
                      ? ib[(size_t)(iy * 14 + ix) * CD] : 0.f;
        }
    }
    float V[36];
    wino4_V(d, V);
    int m = b * NT4 + t;
#pragma unroll
    for (int k = 0; k < 36; k++) {
        size_t off = ((size_t)k * MW4 + m) * CD + ic;
        split_store(V[k], Vh + off, Vl + off);
    }
}

// ---------------- winograd GEMM: M[k][m][oc] = sum_ic V[k][m][ic]*U[k][oc][ic] ----------------
// grid (8 octile, 32 mtile, 36 k), block 256 (8 warps = 4 ocgroups x 2 mhalves)
// fp16 hi/lo 3-MMA split; fragment conventions identical to R12's passing kernel.
template<int IC>
__global__ void __launch_bounds__(256) wino_gemm(const __half* __restrict__ Vh,
                                                 const __half* __restrict__ Vl,
                                                 const __half* __restrict__ Uh,
                                                 const __half* __restrict__ Ul,
                                                 float* __restrict__ Mout) {
    __shared__ uint32_t Ush[16][72], Usl[16][72];   // [icpair][oc64]
    __shared__ uint32_t Vsh[16][136], Vsl[16][136]; // [icpair][m128]

    const int oc0 = blockIdx.x * 64;
    const int m0 = blockIdx.y * 128;
    const int k = blockIdx.z;
    const int tid = threadIdx.x;
    const int warp = tid >> 5, lane = tid & 31;
    const int gid = lane >> 2, tig = lane & 3;
    const int ocw = (warp >> 1) * 16;
    const int mhalf = (warp & 1) * 64;

    float C[8][4];
#pragma unroll
    for (int mt = 0; mt < 8; mt++)
#pragma unroll
        for (int r = 0; r < 4; r++) C[mt][r] = 0.f;

    const __half* Ukh = Uh + (size_t)k * 512 * IC;
    const __half* Ukl = Ul + (size_t)k * 512 * IC;
    const __half* Vkh = Vh + (size_t)k * MW4 * IC;
    const __half* Vkl = Vl + (size_t)k * MW4 * IC;

    for (int ic0 = 0; ic0 < IC; ic0 += 32) {
        __syncthreads();
        for (int e = tid; e < 1024; e += 256) {
            int pr = e & 15, o = e >> 4;
            size_t off = (size_t)(oc0 + o) * IC + ic0 + 2 * pr;
            Ush[pr][o] = *(const uint32_t*)(Ukh + off);
            Usl[pr][o] = *(const uint32_t*)(Ukl + off);
        }
        for (int e = tid; e < 2048; e += 256) {
            int pr = e & 15, m = e >> 4;
            size_t off = (size_t)(m0 + m) * IC + ic0 + 2 * pr;
            Vsh[pr][m] = *(const uint32_t*)(Vkh + off);
            Vsl[pr][m] = *(const uint32_t*)(Vkl + off);
        }
        __syncthreads();
#pragma unroll
        for (int ks = 0; ks < 2; ks++) {
            const int kp = ks * 8;
            uint32_t ahi[4], alo[4];
            ahi[0] = Ush[kp + tig][ocw + gid];
            ahi[1] = Ush[kp + tig][ocw + gid + 8];
            ahi[2] = Ush[kp + 4 + tig][ocw + gid];
            ahi[3] = Ush[kp + 4 + tig][ocw + gid + 8];
            alo[0] = Usl[kp + tig][ocw + gid];
            alo[1] = Usl[kp + tig][ocw + gid + 8];
            alo[2] = Usl[kp + 4 + tig][ocw + gid];
            alo[3] = Usl[kp + 4 + tig][ocw + gid + 8];
#pragma unroll
            for (int mt = 0; mt < 8; mt++) {
                const int mc = mhalf + mt * 8 + gid;
                uint32_t b0h = Vsh[kp + tig][mc];
                uint32_t b1h = Vsh[kp + 4 + tig][mc];
                uint32_t b0l = Vsl[kp + tig][mc];
                uint32_t b1l = Vsl[kp + 4 + tig][mc];
                mma_f16(C[mt], ahi, b0h, b1h);
                mma_f16(C[mt], alo, b0h, b1h);
                mma_f16(C[mt], ahi, b0l, b1l);
            }
        }
    }

    float* Mk = Mout + (size_t)k * MW4 * 512;
#pragma unroll
    for (int mt = 0; mt < 8; mt++) {
        int m = m0 + mhalf + mt * 8 + tig * 2;
        int oc = oc0 + ocw + gid;
        float* mp = Mk + (size_t)m * 512 + oc;
        mp[0] = C[mt][0];
        mp[512] = C[mt][1];
        mp[8] = C[mt][2];
        mp[512 + 8] = C[mt][3];
    }
}

// ---------------- output inverse transform: Y = A^T M A -> out[b][p][c] ----------------
// grid (BB, 16 tiles), block 512 (oc)
template<bool RELU>
__global__ void wino4_out(const float* __restrict__ Min, float* __restrict__ out) {
    int b = blockIdx.x, t = blockIdx.y;
    int oc = threadIdx.x;
    int m = b * NT4 + t;
    float M[36];
#pragma unroll
    for (int k = 0; k < 36; k++) M[k] = Min[((size_t)k * MW4 + m) * 512 + oc];
    float s[4][6];
#pragma unroll
    for (int c = 0; c < 6; c++) {
        float a[6] = {M[c], M[6 + c], M[12 + c], M[18 + c], M[24 + c], M[30 + c]};
        float y[4];
        at6(a, y);
#pragma unroll
        for (int r = 0; r < 4; r++) s[r][c] = y[r];
    }
    int ty = t >> 2, tx = t & 3;
    float* ob = out + (size_t)b * HWD * CD + oc;
#pragma unroll
    for (int r = 0; r < 4; r++) {
        int py = 4 * ty + r;
        if (py >= 14) break;
        float y[4];
        at6(s[r], y);
#pragma unroll
        for (int c = 0; c < 4; c++) {
            int px = 4 * tx + c;
            if (px < 14) {
                float v = y[c];
                if (RELU) v = fmaxf(v, 0.f);
                ob[(size_t)(py * 14 + px) * CD] = v;
            }
        }
    }
}

// ---------------- GEMM: C[m,n] = sum_k A[m,k] * W[n,k], optional relu ----------------
__global__ void gemm_nt(const float* __restrict__ A, const float* __restrict__ W,
                        float* __restrict__ C, int K, int N, int relu) {
    __shared__ float As[16][17], Ws[16][17];
    int tx = threadIdx.x, ty = threadIdx.y;
    int m = blockIdx.y * 16 + ty;
    int n0 = blockIdx.x * 16;
    float acc = 0.f;
    for (int k0 = 0; k0 < K; k0 += 16) {
        As[ty][tx] = A[m * K + k0 + tx];
        Ws[ty][tx] = W[(n0 + ty) * K + k0 + tx];
        __syncthreads();
#pragma unroll
        for (int kk = 0; kk < 16; kk++) acc = fmaf(As[ty][kk], Ws[tx][kk], acc);
        __syncthreads();
    }
    C[m * N + n0 + tx] = relu ? fmaxf(acc, 0.f) : acc;
}

// ---------------- masked mean pooling (fv [b][p][c]) -> ind_vec ----------------
__global__ void indvec_kernel(const float* __restrict__ fv, const int* __restrict__ masks,
                              float* __restrict__ ind) {
    int b = blockIdx.x;
    int c = threadIdx.x;   // 512
    __shared__ float m_s[HWD];
    __shared__ float red[16];
    float mv = 0.f;
    if (c < HWD) { mv = (float)masks[b * HWD + c]; m_s[c] = mv; }
    float tot = blockReduceSum(mv, red);
    float inv_m = 1.f / tot;
    const float* fb = fv + (size_t)b * HWD * CD + c;
    float s = 0.f;
    for (int p = 0; p < HWD; p++) s = fmaf(fb[(size_t)p * CD], m_s[p], s);
    ind[b * CD + c] = s * inv_m;
}

// ---------------- per (b,p) inverse channel L2 norm (fv [b][p][c]) ----------------
__global__ void invrho_kernel(const float* __restrict__ fv, float* __restrict__ invrho) {
    int b = blockIdx.x;
    int lane = threadIdx.x & 31, w = threadIdx.x >> 5;  // 8 warps
    for (int p = w; p < HWD; p += 8) {
        const float* row = fv + ((size_t)b * HWD + p) * CD;
        float s = 0.f;
        for (int c = lane; c < CD; c += 32) { float v = row[c]; s = fmaf(v, v, s); }
        s = warpReduceSum(s);
        if (lane == 0) invrho[b * HWD + p] = 1.f / fmaxf(sqrtf(s), 1e-12f);
    }
}

// ---------------- normalize ind_vec -> ivn (+ transposed copy) ----------------
__global__ void ivn_kernel(const float* __restrict__ ind, float* __restrict__ ivn,
                           float* __restrict__ ivnT) {
    int b = blockIdx.x, c = threadIdx.x;
    __shared__ float red[16];
    float v = ind[b * CD + c];
    float ss = blockReduceSum(v * v, red);
    float o = v / fmaxf(sqrtf(ss), 1e-12f);
    ivn[b * CD + c] = o;
    ivnT[c * BB + b] = o;
}

// ---------------- transpose fa ----------------
__global__ void transpose_fa(const float* __restrict__ fa, float* __restrict__ faT) {
    int idx = blockIdx.x * 256 + threadIdx.x;
    int b = idx >> 9, c = idx & 511;
    faT[c * BB + b] = fa[idx];
}

// ---------------- Sij[i,j,p] = <ivn[j], fv[i,p,:]> * invrho[i,p] ----------------
__global__ void sij_gemm(const float* __restrict__ ivn, const float* __restrict__ fv,
                         const float* __restrict__ invrho, float* __restrict__ Sij) {
    int i = blockIdx.z;
    int p0 = blockIdx.x * 64;
    int j0 = blockIdx.y * 64;
    __shared__ float As[64][17];
    __shared__ float Bs[16][65];
    int tid = threadIdx.y * 16 + threadIdx.x;
    float acc[4][4] = {};
    const float* fvi = fv + (size_t)i * HWD * CD;
    for (int k0 = 0; k0 < CD; k0 += 16) {
#pragma unroll
        for (int r = 0; r < 4; r++) {
            int e = tid + r * 256;
            int row = e >> 4, col = e & 15;
            As[row][col] = ivn[(j0 + row) * CD + k0 + col];
        }
#pragma unroll
        for (int r = 0; r < 4; r++) {
            int e = tid + r * 256;
            int cs = e & 15, p = e >> 4;
            int pg = p0 + p;
            Bs[cs][p] = (pg < HWD) ? fvi[(size_t)pg * CD + k0 + cs] : 0.f;
        }
        __syncthreads();
#pragma unroll
        for (int kk = 0; kk < 16; kk++) {
            float a[4], bb[4];
#pragma unroll
            for (int r = 0; r < 4; r++) a[r] = As[threadIdx.y * 4 + r][kk];
#pragma unroll
            for (int c = 0; c < 4; c++) bb[c] = Bs[kk][threadIdx.x * 4 + c];
#pragma unroll
            for (int r = 0; r < 4; r++)
#pragma unroll
                for (int c = 0; c < 4; c++)
                    acc[r][c] = fmaf(a[r], bb[c], acc[r][c]);
        }
        __syncthreads();
    }
#pragma unroll
    for (int r = 0; r < 4; r++) {
        int j = j0 + threadIdx.y * 4 + r;
#pragma unroll
        for (int c = 0; c < 4; c++) {
            int p = p0 + threadIdx.x * 4 + c;
            if (p < HWD)
                Sij[((size_t)(i * BB + j)) * HWD + p] = acc[r][c] * invrho[i * HWD + p];
        }
    }
}

// ---------------- warp-per-row dual radix-select + soft-mask pooling ----------------
__global__ void topk_radix(const float* __restrict__ Sij, float* __restrict__ SP,
                           float* __restrict__ SN) {
    int row = (blockIdx.x * blockDim.x + threadIdx.x) >> 5;
    int lane = threadIdx.x & 31;
    const float* rp = Sij + (size_t)row * HWD;

    float v[7];
    uint32_t key[7];
#pragma unroll
    for (int e = 0; e < 7; e++) {
        int p = e * 32 + lane;
        bool valid = (p < HWD);
        v[e] = valid ? rp[p] : 0.f;
        key[e] = valid ? f2key(v[e]) : 0u;
    }

    uint32_t p1 = 0, p2 = 0;
#pragma unroll
    for (int b = 31; b >= 0; b--) {
        uint32_t c1 = (p1 >> b) | 1u;
        uint32_t c2 = (p2 >> b) | 1u;
        int n = 0;
#pragma unroll
        for (int e = 0; e < 7; e++) {
            uint32_t t = key[e] >> b;
            n += (t >= c1) ? 1 : 0;
            n += (t >= c2) ? 0x10000 : 0;
        }
        n = __reduce_add_sync(0xffffffffu, n);
        if ((n & 0xffff) >= 19) p1 |= (1u << b);
        if ((n >> 16) >= 99)    p2 |= (1u << b);
    }
    float pthr = key2f(p1);
    float nthr = key2f(p2);

    float svp = 0.f, sp = 0.f, svn = 0.f, sn = 0.f;
#pragma unroll
    for (int e = 0; e < 7; e++) {
        int p = e * 32 + lane;
        if (p < HWD) {
            float mp = sigmoidf_stable((v[e] - pthr) * TS_INV);
            float mn = 1.f - sigmoidf_stable((v[e] - nthr) * TS_INV);
            svp += v[e] * mp; sp += mp;
            svn += v[e] * mn; sn += mn;
        }
    }
    svp = warpReduceSum(svp); sp = warpReduceSum(sp);
    svn = warpReduceSum(svn); sn = warpReduceSum(sn);
    if (lane == 0) {
        SP[row] = svp / sp;
        SN[row] = svn / sn;
    }
}

// ---------------- contrastive losses ----------------
__global__ void loss12_kernel(const float* __restrict__ SP, const float* __restrict__ SN,
                              float* __restrict__ l1, float* __restrict__ l2) {
    int i = blockIdx.x, j = threadIdx.x;
    __shared__ float red[8];
    float a1 = SP[i * BB + j] * TC_INV, a2 = SN[i * BB + j] * TC_INV;
    float b1 = SP[j * BB + i] * TC_INV, b2 = SN[j * BB + i] * TC_INV;
    float m1 = blockReduceMax(fmaxf(a1, a2), red);
    float s1 = blockReduceSum(expf(a1 - m1) + expf(a2 - m1), red);
    float m2 = blockReduceMax(fmaxf(b1, b2), red);
    float s2 = blockReduceSum(expf(b1 - m2) + expf(b2 - m2), red);
    if (j == 0) {
        float diag = SP[i * BB + i] * TC_INV;
        l1[i] = logf(s1) + m1 - diag;
        l2[i] = logf(s2) + m2 - diag;
    }
}

// ---------------- weighted pairwise-distance matrix E ----------------
__global__ void dist_kernel(const float* __restrict__ ind, const float* __restrict__ ivn,
                            const float* __restrict__ faT, const float* __restrict__ ivnT,
                            float* __restrict__ E) {
    int i = blockIdx.x, j = threadIdx.x;
    __shared__ float ind_s[CD], ivn_s[CD];
    for (int c = j; c < CD; c += 256) { ind_s[c] = ind[i * CD + c]; ivn_s[c] = ivn[i * CD + c]; }
    __syncthreads();
    float d = 0.f, vv = 0.f;
    for (int c = 0; c < CD; c++) {
        float t = ind_s[c] - faT[c * BB + j] + 1e-6f;
        d = fmaf(t, t, d);
        vv = fmaf(ivn_s[c], ivnT[c * BB + j], vv);
    }
    E[i * BB + j] = (i == j) ? d : d * vv * (1.f / 255.f);
}

// ---------------- final scalar losses ----------------
__global__ void final_kernel(const float* __restrict__ E, const float* __restrict__ l1,
                             const float* __restrict__ l2, float* __restrict__ out) {
    int t = threadIdx.x;
    __shared__ float red[8];
    float r = 0.f, c = 0.f;
    for (int j = 0; j < BB; j++) r += E[t * BB + j];
    for (int i2 = 0; i2 < BB; i2++) c += E[i2 * BB + t];
    float a3 = fmaxf(r + 0.6f, 0.f);
    float a4 = fmaxf(c + 0.6f, 0.f);
    float s3 = blockReduceSum(a3, red);
    float s4 = blockReduceSum(a4, red);
    float s1 = blockReduceSum(l1[t], red);
    float s2 = blockReduceSum(l2[t], red);
    if (t == 0) {
        out[0] = (s1 + s2) * (0.5f / (float)BB);
        out[1] = (s3 + s4) * (0.5f / (float)BB);
    }
}

// ---------------- launch ----------------
extern "C" void kernel_launch(void* const* d_in, const int* in_sizes, int n_in,
                              void* d_out, int out_size) {
    const float* ev   = (const float*)d_in[0];
    const float* ea   = (const float*)d_in[1];
    const int*   masks= (const int*)  d_in[2];
    const float* Wfc1 = (const float*)d_in[3];
    const float* Wfc2 = (const float*)d_in[4];
    const float* Wc1  = (const float*)d_in[5];
    const float* Wc2  = (const float*)d_in[6];
    float* out = (float*)d_out;

    float *hfc, *fa, *faT, *h1, *fv, *ind, *ivn, *ivnT, *invrho, *Sij, *SP, *SN, *E, *l1, *l2, *M;
    __half *Vh, *Vl, *U1h, *U1l, *U2h, *U2l;
    cudaGetSymbolAddress((void**)&hfc,    d_hfc);
    cudaGetSymbolAddress((void**)&fa,     d_fa);
    cudaGetSymbolAddress((void**)&faT,    d_faT);
    cudaGetSymbolAddress((void**)&h1,     d_h1);
    cudaGetSymbolAddress((void**)&fv,     d_fv);
    cudaGetSymbolAddress((void**)&ind,    d_ind);
    cudaGetSymbolAddress((void**)&ivn,    d_ivn);
    cudaGetSymbolAddress((void**)&ivnT,   d_ivnT);
    cudaGetSymbolAddress((void**)&invrho, d_invrho);
    cudaGetSymbolAddress((void**)&Sij,    d_Sij);
    cudaGetSymbolAddress((void**)&SP,     d_SP);
    cudaGetSymbolAddress((void**)&SN,     d_SN);
    cudaGetSymbolAddress((void**)&E,      d_E);
    cudaGetSymbolAddress((void**)&l1,     d_l1);
    cudaGetSymbolAddress((void**)&l2,     d_l2);
    cudaGetSymbolAddress((void**)&M,      d_M);
    cudaGetSymbolAddress((void**)&Vh,     d_Vh);
    cudaGetSymbolAddress((void**)&Vl,     d_Vl);
    cudaGetSymbolAddress((void**)&U1h,    d_U1h);
    cudaGetSymbolAddress((void**)&U1l,    d_U1l);
    cudaGetSymbolAddress((void**)&U2h,    d_U2h);
    cudaGetSymbolAddress((void**)&U2l,    d_U2l);

    // conv chain first (wino_gemm<384> at launch index 3 -> gets the ncu capture)
    wino4_wprep<<<(512 * 384 + 255) / 256, 256>>>(Wc1, U1h, U1l, 384);
    wino4_wprep<<<(512 * 512 + 255) / 256, 256>>>(Wc2, U2h, U2l, 512);
    wino4_in_nchw<<<dim3(BB, 384 / 16), 256>>>(ev, Vh, Vl, 384);
    wino_gemm<384><<<dim3(8, 32, 36), 256>>>(Vh, Vl, U1h, U1l, M);
    wino4_out<true><<<dim3(BB, NT4), 512>>>(M, h1);

    wino4_in_pc<<<dim3(BB, NT4), 512>>>(h1, Vh, Vl);
    wino_gemm<512><<<dim3(8, 32, 36), 256>>>(Vh, Vl, U2h, U2l, M);
    wino4_out<false><<<dim3(BB, NT4), 512>>>(M, fv);

    // audio branch
    gemm_nt<<<dim3(CD / 16, BB / 16), dim3(16, 16)>>>(ea, Wfc1, hfc, 2048, CD, 1);
    gemm_nt<<<dim3(CD / 16, BB / 16), dim3(16, 16)>>>(hfc, Wfc2, fa, CD, CD, 0);
    transpose_fa<<<512, 256>>>(fa, faT);

    // pooling / norms
    indvec_kernel<<<BB, 512>>>(fv, masks, ind);
    invrho_kernel<<<BB, 256>>>(fv, invrho);
    ivn_kernel<<<BB, CD>>>(ind, ivn, ivnT);

    // similarity tensor + exact top-k soft pooling
    sij_gemm<<<dim3(4, 4, BB), dim3(16, 16)>>>(ivn, fv, invrho, Sij);
    topk_radix<<<(BB * BB) / 8, 256>>>(Sij, SP, SN);

    // losses
    loss12_kernel<<<BB, 256>>>(SP, SN, l1, l2);
    dist_kernel<<<BB, 256>>>(ind, ivn, faT, ivnT, E);
    final_kernel<<<1, 256>>>(E, l1, l2, out);
}